// round 2
// baseline (speedup 1.0000x reference)
#include <cuda_runtime.h>
#include <math.h>

#define NT 16384
#define DM 256
#define DI 512
#define DS 64
#define NH 8
#define HD 64
#define CD 640      // CONV_DIM
#define DP 1160     // D_PROJ
#define KER 4
#define NCH 256     // number of chunks
#define CQ 64       // chunk length
#define P65 65      // padded row stride for 64x64 smem tiles

// ---------------- device scratch (no allocations allowed) ----------------
__device__ float g_q[NT * DM];
__device__ float g_qn[NT * DM];
__device__ float g_Z[NT * DP];           // in_proj output (token order, shared by both serializations)
__device__ float g_XBC[2 * NT * CD];     // conv output (rank order, per batch)
__device__ float g_dt[2 * NT * NH];
__device__ float g_a[2 * NT * NH];       // dt * A
__device__ float g_cum[2 * NH * NCH * CQ];
__device__ float g_cdec[2 * NH * NCH];
__device__ float g_S[2 * NH * NCH * HD * DS];   // per-chunk state contribution
__device__ float g_Hp[2 * NH * NCH * HD * DS];  // state BEFORE each chunk
__device__ float g_Y[2 * NT * DI];
__device__ float g_comb[NT * DI];
__device__ float g_O[NT * DM];
__device__ unsigned long long g_keys[2 * NT];
__device__ int g_order[2 * NT];
__device__ int g_inv[2 * NT];
__device__ float g_pmin[3], g_pmax[3];

// ---------------- helpers ----------------
__device__ __forceinline__ float blockReduceSum(float v) {
    __shared__ float sh[32];
    __shared__ float tot;
    int lane = threadIdx.x & 31, wid = threadIdx.x >> 5;
    #pragma unroll
    for (int o = 16; o > 0; o >>= 1) v += __shfl_xor_sync(0xffffffffu, v, o);
    if (lane == 0) sh[wid] = v;
    __syncthreads();
    int nw = blockDim.x >> 5;
    v = (threadIdx.x < nw) ? sh[threadIdx.x] : 0.0f;
    if (wid == 0) {
        #pragma unroll
        for (int o = 16; o > 0; o >>= 1) v += __shfl_xor_sync(0xffffffffu, v, o);
        if (lane == 0) tot = v;
    }
    __syncthreads();
    return tot;
}

__device__ __forceinline__ unsigned hilbert3(unsigned a0, unsigned a1, unsigned a2) {
    unsigned x0 = a0, x1 = a1, x2 = a2;
    const unsigned M = 1u << 9;
    for (unsigned Q = M; Q > 1; Q >>= 1) {
        unsigned P = Q - 1;
        // i = 0
        if (x0 & Q) x0 ^= P;
        // i = 1
        {
            unsigned t = (x0 ^ x1) & P;
            if (x1 & Q) { x0 ^= P; } else { x0 ^= t; x1 ^= t; }
        }
        // i = 2
        {
            unsigned t = (x0 ^ x2) & P;
            if (x2 & Q) { x0 ^= P; } else { x0 ^= t; x2 ^= t; }
        }
    }
    x1 ^= x0;
    x2 ^= x1;
    unsigned t = 0;
    for (unsigned Q = M; Q > 1; Q >>= 1)
        if (x2 & Q) t ^= (Q - 1);
    x0 ^= t; x1 ^= t; x2 ^= t;
    unsigned code = 0;
    for (int b = 9; b >= 0; b--) {
        code = (code << 1) | ((x0 >> b) & 1);
        code = (code << 1) | ((x1 >> b) & 1);
        code = (code << 1) | ((x2 >> b) & 1);
    }
    return code;
}

// ---------------- kernels ----------------
__global__ void k_copy(const float* __restrict__ src) {
    int i = blockIdx.x * blockDim.x + threadIdx.x;
    if (i < NT * DM) g_q[i] = src[i];
}

__global__ void k_minmax(const float* __restrict__ pos) {
    __shared__ float smn[256][3], smx[256][3];
    float mn[3] = {1e30f, 1e30f, 1e30f}, mx[3] = {-1e30f, -1e30f, -1e30f};
    for (int r = threadIdx.x; r < NT; r += 256) {
        #pragma unroll
        for (int j = 0; j < 3; j++) {
            float v = pos[r * 3 + j];
            mn[j] = fminf(mn[j], v);
            mx[j] = fmaxf(mx[j], v);
        }
    }
    #pragma unroll
    for (int j = 0; j < 3; j++) { smn[threadIdx.x][j] = mn[j]; smx[threadIdx.x][j] = mx[j]; }
    __syncthreads();
    for (int s = 128; s > 0; s >>= 1) {
        if (threadIdx.x < s) {
            #pragma unroll
            for (int j = 0; j < 3; j++) {
                smn[threadIdx.x][j] = fminf(smn[threadIdx.x][j], smn[threadIdx.x + s][j]);
                smx[threadIdx.x][j] = fmaxf(smx[threadIdx.x][j], smx[threadIdx.x + s][j]);
            }
        }
        __syncthreads();
    }
    if (threadIdx.x == 0) {
        #pragma unroll
        for (int j = 0; j < 3; j++) { g_pmin[j] = smn[0][j]; g_pmax[j] = smx[0][j]; }
    }
}

__global__ void k_keys(const float* __restrict__ pos) {
    int idx = blockIdx.x * blockDim.x + threadIdx.x;
    if (idx >= NT) return;
    unsigned g[3];
    #pragma unroll
    for (int j = 0; j < 3; j++) {
        float denom = g_pmax[j] - g_pmin[j] + 1e-6f;
        float v = ((pos[idx * 3 + j] - g_pmin[j]) / denom) * 1023.0f;
        v = fminf(fmaxf(v, 0.0f), 1023.0f);
        g[j] = (unsigned)(int)v;
    }
    unsigned c0 = hilbert3(g[0], g[1], g[2]);
    unsigned c1 = hilbert3(g[1], g[0], g[2]);
    g_keys[idx]      = (((unsigned long long)c0) << 14) | (unsigned long long)idx;
    g_keys[NT + idx] = (((unsigned long long)c1) << 14) | (unsigned long long)idx;
}

extern __shared__ unsigned long long s_sort[];
__global__ void k_sort() {
    unsigned long long* keys = g_keys + blockIdx.x * NT;
    for (int i = threadIdx.x; i < NT; i += blockDim.x) s_sort[i] = keys[i];
    __syncthreads();
    for (int k = 2; k <= NT; k <<= 1) {
        for (int j = k >> 1; j > 0; j >>= 1) {
            for (int i = threadIdx.x; i < NT; i += blockDim.x) {
                int ixj = i ^ j;
                if (ixj > i) {
                    unsigned long long a = s_sort[i], b = s_sort[ixj];
                    bool up = ((i & k) == 0);
                    if ((a > b) == up) { s_sort[i] = b; s_sort[ixj] = a; }
                }
            }
            __syncthreads();
        }
    }
    for (int i = threadIdx.x; i < NT; i += blockDim.x) keys[i] = s_sort[i];
}

__global__ void k_order() {
    int i = blockIdx.x * blockDim.x + threadIdx.x;
    if (i >= 2 * NT) return;
    int b = i / NT;
    int idx = (int)(g_keys[i] & 0x3FFFULL);
    g_order[i] = idx;
    g_inv[b * NT + idx] = i - b * NT;
}

__global__ void k_ln256(const float* __restrict__ w, const float* __restrict__ bias) {
    int r = blockIdx.x, c = threadIdx.x;
    float v = g_q[r * DM + c];
    float mean = blockReduceSum(v) * (1.0f / DM);
    float xc = v - mean;
    float var = blockReduceSum(xc * xc) * (1.0f / DM);
    g_qn[r * DM + c] = xc * rsqrtf(var + 1e-5f) * w[c] + bias[c];
}

// generic fp32 NN GEMM: C[M,N] = A[M,K] @ B[K,N]; M%64==0, K%16==0
__global__ void k_gemm(int M, int N, int K,
                       const float* __restrict__ A, int lda,
                       const float* __restrict__ B, int ldb,
                       float* __restrict__ C, int ldc) {
    __shared__ float sA[16][65];
    __shared__ float sB[16][64];
    int m0 = blockIdx.y * 64, n0 = blockIdx.x * 64;
    int tid = threadIdx.x;
    int tm = tid >> 4, tn = tid & 15;
    int arow = tid >> 2, akg = (tid & 3) * 4;
    int bkk = tid >> 4, bng = (tid & 15) * 4;
    float acc[4][4] = {};
    for (int k0 = 0; k0 < K; k0 += 16) {
        float4 a4 = *(const float4*)(A + (size_t)(m0 + arow) * lda + k0 + akg);
        sA[akg + 0][arow] = a4.x; sA[akg + 1][arow] = a4.y;
        sA[akg + 2][arow] = a4.z; sA[akg + 3][arow] = a4.w;
        if (n0 + bng + 3 < N) {
            *(float4*)&sB[bkk][bng] = *(const float4*)(B + (size_t)(k0 + bkk) * ldb + n0 + bng);
        } else {
            #pragma unroll
            for (int j = 0; j < 4; j++)
                sB[bkk][bng + j] = (n0 + bng + j < N) ? B[(size_t)(k0 + bkk) * ldb + n0 + bng + j] : 0.0f;
        }
        __syncthreads();
        #pragma unroll
        for (int kk = 0; kk < 16; kk++) {
            float a[4], b[4];
            #pragma unroll
            for (int i = 0; i < 4; i++) a[i] = sA[kk][tm * 4 + i];
            #pragma unroll
            for (int j = 0; j < 4; j++) b[j] = sB[kk][tn * 4 + j];
            #pragma unroll
            for (int i = 0; i < 4; i++)
                #pragma unroll
                for (int j = 0; j < 4; j++)
                    acc[i][j] += a[i] * b[j];
        }
        __syncthreads();
    }
    #pragma unroll
    for (int i = 0; i < 4; i++)
        #pragma unroll
        for (int j = 0; j < 4; j++) {
            int n = n0 + tn * 4 + j;
            if (n < N) C[(size_t)(m0 + tm * 4 + i) * ldc + n] = acc[i][j];
        }
}

__global__ void k_conv(const float* __restrict__ cw, const float* __restrict__ cb) {
    int r = blockIdx.x, b = blockIdx.y;
    __shared__ int tok[KER];
    if (threadIdx.x < KER) {
        int rr = r - (KER - 1) + threadIdx.x;
        tok[threadIdx.x] = (rr >= 0) ? g_order[b * NT + rr] : -1;
    }
    __syncthreads();
    for (int c = threadIdx.x; c < CD; c += blockDim.x) {
        float acc = cb[c];
        #pragma unroll
        for (int k = 0; k < KER; k++) {
            int t = tok[k];
            if (t >= 0) acc += cw[c * KER + k] * g_Z[t * DP + DI + c];
        }
        float s = acc / (1.0f + expf(-acc));
        g_XBC[(b * NT + r) * CD + c] = s;
    }
}

__global__ void k_dt(const float* __restrict__ dtb, const float* __restrict__ alog) {
    int i = blockIdx.x * blockDim.x + threadIdx.x;
    if (i >= 2 * NT * NH) return;
    int b = i / (NT * NH);
    int rem = i - b * NT * NH;
    int r = rem / NH, h = rem - r * NH;
    int t = g_order[b * NT + r];
    float x = g_Z[t * DP + DI + CD + h] + dtb[h];
    float sp = fmaxf(x, 0.0f) + log1pf(expf(-fabsf(x)));
    float A = -expf(alog[h]);
    g_dt[i] = sp;
    g_a[i] = sp * A;
}

// chunk cumsum + per-chunk state contribution S[p][s]
__global__ void k_scan1() {
    int c = blockIdx.x, h = blockIdx.y, b = blockIdx.z;
    int r0 = c * CQ, tid = threadIdx.x;
    __shared__ float scum[CQ], sw[CQ];
    __shared__ float sX[CQ][HD], sBm[CQ][DS];
    if (tid < CQ) scum[tid] = g_a[(b * NT + r0 + tid) * NH + h];
    __syncthreads();
    if (tid == 0) {
        float s = 0.0f;
        for (int i = 0; i < CQ; i++) { s += scum[i]; scum[i] = s; }
    }
    __syncthreads();
    float slast = scum[CQ - 1];
    if (tid < CQ) {
        sw[tid] = expf(slast - scum[tid]) * g_dt[(b * NT + r0 + tid) * NH + h];
        g_cum[((b * NH + h) * NCH + c) * CQ + tid] = scum[tid];
    }
    if (tid == 0) g_cdec[(b * NH + h) * NCH + c] = expf(slast);
    for (int idx = tid; idx < CQ * HD; idx += 256) {
        int j = idx >> 6, p = idx & 63;
        sX[j][p]  = g_XBC[(b * NT + r0 + j) * CD + h * HD + p];
        sBm[j][p] = g_XBC[(b * NT + r0 + j) * CD + DI + p];
    }
    __syncthreads();
    int p = tid & 63, s0 = (tid >> 6) * 16;
    float acc[16] = {};
    for (int j = 0; j < CQ; j++) {
        float xw = sX[j][p] * sw[j];
        #pragma unroll
        for (int k = 0; k < 16; k++) acc[k] += xw * sBm[j][s0 + k];
    }
    int base = (((b * NH + h) * NCH + c) * HD + p) * DS + s0;
    #pragma unroll
    for (int k = 0; k < 16; k++) g_S[base + k] = acc[k];
}

// inter-chunk recurrence: only 256 sequential steps, parallel over states
__global__ void k_scan2() {
    int bh = blockIdx.x, tid = threadIdx.x;
    float H0 = 0.f, H1 = 0.f, H2 = 0.f, H3 = 0.f;
    int e = tid * 4;
    for (int c = 0; c < NCH; c++) {
        float cd = g_cdec[bh * NCH + c];
        int off = (bh * NCH + c) * HD * DS + e;
        float4 s4 = *(const float4*)(g_S + off);
        *(float4*)(g_Hp + off) = make_float4(H0, H1, H2, H3);
        H0 = cd * H0 + s4.x; H1 = cd * H1 + s4.y;
        H2 = cd * H2 + s4.z; H3 = cd * H3 + s4.w;
    }
}

// per-chunk outputs: intra (G@X) + inter (C@Hprev) + D*x
extern __shared__ float s3[];
__global__ void k_scan3(const float* __restrict__ Dv) {
    int c = blockIdx.x, h = blockIdx.y, b = blockIdx.z;
    int r0 = c * CQ, tid = threadIdx.x;
    float* sC = s3;
    float* sB = sC + CQ * P65;
    float* sG = sB + CQ * P65;
    float* sX = sG + CQ * P65;
    float* sH = sX + CQ * P65;
    float* scum = sH + CQ * P65;
    float* sdt = scum + CQ;
    int hbase = (((b * NH + h) * NCH + c) * HD) * DS;
    for (int idx = tid; idx < CQ * HD; idx += 256) {
        int j = idx >> 6, p = idx & 63;
        sC[j * P65 + p] = g_XBC[(b * NT + r0 + j) * CD + DI + DS + p];
        sB[j * P65 + p] = g_XBC[(b * NT + r0 + j) * CD + DI + p];
        sX[j * P65 + p] = g_XBC[(b * NT + r0 + j) * CD + h * HD + p];
        sH[j * P65 + p] = g_Hp[hbase + idx];   // sH[p_row][s]
    }
    if (tid < CQ) {
        scum[tid] = g_cum[((b * NH + h) * NCH + c) * CQ + tid];
        sdt[tid] = g_dt[(b * NT + r0 + tid) * NH + h];
    }
    __syncthreads();
    // phase 1: G[i][j] = exp(cum_i - cum_j) * dt_j * (C_i . B_j), j <= i
    for (int idx = tid; idx < CQ * CQ; idx += 256) {
        int i = idx >> 6, j = idx & 63;
        float v = 0.0f;
        if (j <= i) {
            float d = 0.0f;
            #pragma unroll 8
            for (int s = 0; s < DS; s++) d += sC[i * P65 + s] * sB[j * P65 + s];
            v = expf(scum[i] - scum[j]) * sdt[j] * d;
        }
        sG[i * P65 + j] = v;
    }
    __syncthreads();
    // phase 2: Y[i][p]
    int p = tid & 63, ib = tid >> 6;
    float accY[16];
    float Dh = Dv[h];
    #pragma unroll
    for (int k = 0; k < 16; k++) {
        int i = ib * 16 + k;
        float d = 0.0f;
        #pragma unroll 8
        for (int s = 0; s < DS; s++) d += sC[i * P65 + s] * sH[p * P65 + s];
        accY[k] = expf(scum[i]) * d;
    }
    for (int j = 0; j < CQ; j++) {
        float xv = sX[j * P65 + p];
        #pragma unroll
        for (int k = 0; k < 16; k++) accY[k] += sG[(ib * 16 + k) * P65 + j] * xv;
    }
    #pragma unroll
    for (int k = 0; k < 16; k++) {
        int i = ib * 16 + k;
        float y = accY[k] + Dh * sX[i * P65 + p];
        g_Y[(b * NT + r0 + i) * DI + h * HD + p] = y;
    }
}

__global__ void k_postnorm(const float* __restrict__ nw) {
    int r = blockIdx.x, b = blockIdx.y, tid = threadIdx.x;
    int t = g_order[b * NT + r];
    float v0, v1, ss;
    {
        float y0 = g_Y[(b * NT + r) * DI + tid];
        float g0 = g_Z[t * DP + tid];
        v0 = y0 * (g0 / (1.0f + expf(-g0)));
        float y1 = g_Y[(b * NT + r) * DI + tid + 256];
        float g1 = g_Z[t * DP + tid + 256];
        v1 = y1 * (g1 / (1.0f + expf(-g1)));
        ss = v0 * v0 + v1 * v1;
    }
    ss = blockReduceSum(ss);
    float rr = rsqrtf(ss * (1.0f / DI) + 1e-5f);
    g_Y[(b * NT + r) * DI + tid]       = v0 * rr * nw[tid];
    g_Y[(b * NT + r) * DI + tid + 256] = v1 * rr * nw[tid + 256];
}

__global__ void k_combine() {
    int t = blockIdx.x, c = threadIdx.x;  // 512 threads
    int r0 = g_inv[t], r1 = g_inv[NT + t];
    g_comb[t * DI + c] = 0.5f * (g_Y[r0 * DI + c] + g_Y[(NT + r1) * DI + c]);
}

__global__ void k_final(const float* __restrict__ w, const float* __restrict__ bias,
                        float* __restrict__ dout) {
    int r = blockIdx.x, c = threadIdx.x;
    float v = g_q[r * DM + c] + g_O[r * DM + c];
    float mean = blockReduceSum(v) * (1.0f / DM);
    float xc = v - mean;
    float var = blockReduceSum(xc * xc) * (1.0f / DM);
    float res = xc * rsqrtf(var + 1e-5f) * w[c] + bias[c];
    g_q[r * DM + c] = res;
    if (dout) dout[r * DM + c] = res;
}

// ---------------- launcher ----------------
extern "C" void kernel_launch(void* const* d_in, const int* in_sizes, int n_in,
                              void* d_out, int out_size) {
    (void)in_sizes; (void)n_in; (void)out_size;
    const float* query = (const float*)d_in[0];
    const float* pos   = (const float*)d_in[1];
    const float* pre_w = (const float*)d_in[2];
    const float* pre_b = (const float*)d_in[3];
    const float* fin_w = (const float*)d_in[4];
    const float* fin_b = (const float*)d_in[5];

    cudaFuncSetAttribute(k_sort, cudaFuncAttributeMaxDynamicSharedMemorySize, NT * 8);
    cudaFuncSetAttribute(k_scan3, cudaFuncAttributeMaxDynamicSharedMemorySize, 84 * 1024);

    float *p_qn, *p_Z, *p_comb, *p_O;
    cudaGetSymbolAddress((void**)&p_qn, g_qn);
    cudaGetSymbolAddress((void**)&p_Z, g_Z);
    cudaGetSymbolAddress((void**)&p_comb, g_comb);
    cudaGetSymbolAddress((void**)&p_O, g_O);

    k_copy<<<(NT * DM + 255) / 256, 256>>>(query);
    k_minmax<<<1, 256>>>(pos);
    k_keys<<<(NT + 255) / 256, 256>>>(pos);
    k_sort<<<2, 1024, NT * 8>>>();
    k_order<<<(2 * NT + 255) / 256, 256>>>();

    for (int L = 0; L < 2; L++) {
        const float* Win  = (const float*)d_in[6 + 8 * L];
        const float* cw   = (const float*)d_in[7 + 8 * L];
        const float* cb   = (const float*)d_in[8 + 8 * L];
        const float* dtb  = (const float*)d_in[9 + 8 * L];
        const float* alog = (const float*)d_in[10 + 8 * L];
        const float* Dv   = (const float*)d_in[11 + 8 * L];
        const float* nw   = (const float*)d_in[12 + 8 * L];
        const float* Wout = (const float*)d_in[13 + 8 * L];

        k_ln256<<<NT, 256>>>(pre_w, pre_b);
        k_gemm<<<dim3((DP + 63) / 64, NT / 64), 256>>>(NT, DP, DM, p_qn, DM, Win, DP, p_Z, DP);
        k_conv<<<dim3(NT, 2), 256>>>(cw, cb);
        k_dt<<<(2 * NT * NH + 255) / 256, 256>>>(dtb, alog);
        k_scan1<<<dim3(NCH, NH, 2), 256>>>();
        k_scan2<<<16, 1024>>>();
        k_scan3<<<dim3(NCH, NH, 2), 256, (5 * CQ * P65 + 2 * CQ) * 4>>>(Dv);
        k_postnorm<<<dim3(NT, 2), 256>>>(nw);
        k_combine<<<NT, 512>>>();
        k_gemm<<<dim3(DM / 64, NT / 64), 256>>>(NT, DM, DI, p_comb, DI, Wout, DM, p_O, DM);
        k_final<<<NT, 256>>>(fin_w, fin_b, (L == 1) ? (float*)d_out : nullptr);
    }
}

// round 3
// speedup vs baseline: 1.3846x; 1.3846x over previous
#include <cuda_runtime.h>
#include <math.h>

#define NT 16384
#define DM 256
#define DI 512
#define DS 64
#define NH 8
#define HD 64
#define CD 640      // CONV_DIM
#define DP 1160     // D_PROJ
#define KER 4
#define NCH 256     // number of chunks
#define CQ 64       // chunk length
#define SR 68       // padded row stride for 64-col smem tiles (float4-aligned)
#define SA_STRIDE 132
#define SB_STRIDE 68

// ---------------- device scratch (no allocations allowed) ----------------
__device__ float g_q[NT * DM];
__device__ float g_qn[NT * DM];
__device__ float g_Z[NT * DP];
__device__ float g_XBC[2 * NT * CD];
__device__ float g_dt[2 * NT * NH];
__device__ float g_a[2 * NT * NH];
__device__ float g_cum[2 * NH * NCH * CQ];
__device__ float g_cdec[2 * NH * NCH];
__device__ float g_S[2 * NH * NCH * HD * DS];
__device__ float g_Hp[2 * NH * NCH * HD * DS];
__device__ float g_Y[2 * NT * DI];
__device__ float g_comb[NT * DI];
__device__ float g_O[NT * DM];
__device__ unsigned long long g_keys[2 * NT];
__device__ int g_order[2 * NT];
__device__ int g_inv[2 * NT];
__device__ float g_pmin[3], g_pmax[3];

extern __shared__ float dynsmem[];

// ---------------- helpers ----------------
__device__ __forceinline__ float blockReduceSum(float v) {
    __shared__ float sh[32];
    __shared__ float tot;
    int lane = threadIdx.x & 31, wid = threadIdx.x >> 5;
    #pragma unroll
    for (int o = 16; o > 0; o >>= 1) v += __shfl_xor_sync(0xffffffffu, v, o);
    if (lane == 0) sh[wid] = v;
    __syncthreads();
    int nw = blockDim.x >> 5;
    v = (threadIdx.x < nw) ? sh[threadIdx.x] : 0.0f;
    if (wid == 0) {
        #pragma unroll
        for (int o = 16; o > 0; o >>= 1) v += __shfl_xor_sync(0xffffffffu, v, o);
        if (lane == 0) tot = v;
    }
    __syncthreads();
    return tot;
}

__device__ __forceinline__ unsigned hilbert3(unsigned a0, unsigned a1, unsigned a2) {
    unsigned x0 = a0, x1 = a1, x2 = a2;
    const unsigned M = 1u << 9;
    for (unsigned Q = M; Q > 1; Q >>= 1) {
        unsigned P = Q - 1;
        if (x0 & Q) x0 ^= P;
        {
            unsigned t = (x0 ^ x1) & P;
            if (x1 & Q) { x0 ^= P; } else { x0 ^= t; x1 ^= t; }
        }
        {
            unsigned t = (x0 ^ x2) & P;
            if (x2 & Q) { x0 ^= P; } else { x0 ^= t; x2 ^= t; }
        }
    }
    x1 ^= x0;
    x2 ^= x1;
    unsigned t = 0;
    for (unsigned Q = M; Q > 1; Q >>= 1)
        if (x2 & Q) t ^= (Q - 1);
    x0 ^= t; x1 ^= t; x2 ^= t;
    unsigned code = 0;
    for (int b = 9; b >= 0; b--) {
        code = (code << 1) | ((x0 >> b) & 1);
        code = (code << 1) | ((x1 >> b) & 1);
        code = (code << 1) | ((x2 >> b) & 1);
    }
    return code;
}

__device__ __forceinline__ unsigned f2tf32(float x) {
    unsigned u;
    asm("cvt.rna.tf32.f32 %0, %1;" : "=r"(u) : "f"(x));
    return u;
}

__device__ __forceinline__ void mma_tf32(float c[4], const unsigned a[4],
                                         unsigned b0, unsigned b1) {
    asm volatile("mma.sync.aligned.m16n8k8.row.col.f32.tf32.tf32.f32 "
        "{%0,%1,%2,%3}, {%4,%5,%6,%7}, {%8,%9}, {%0,%1,%2,%3};"
        : "+f"(c[0]), "+f"(c[1]), "+f"(c[2]), "+f"(c[3])
        : "r"(a[0]), "r"(a[1]), "r"(a[2]), "r"(a[3]), "r"(b0), "r"(b1));
}

// ---------------- setup kernels ----------------
__global__ void k_copy(const float* __restrict__ src) {
    int i = blockIdx.x * blockDim.x + threadIdx.x;
    if (i < NT * DM) g_q[i] = src[i];
}

__global__ void k_minmax(const float* __restrict__ pos) {
    __shared__ float smn[256][3], smx[256][3];
    float mn[3] = {1e30f, 1e30f, 1e30f}, mx[3] = {-1e30f, -1e30f, -1e30f};
    for (int r = threadIdx.x; r < NT; r += 256) {
        #pragma unroll
        for (int j = 0; j < 3; j++) {
            float v = pos[r * 3 + j];
            mn[j] = fminf(mn[j], v);
            mx[j] = fmaxf(mx[j], v);
        }
    }
    #pragma unroll
    for (int j = 0; j < 3; j++) { smn[threadIdx.x][j] = mn[j]; smx[threadIdx.x][j] = mx[j]; }
    __syncthreads();
    for (int s = 128; s > 0; s >>= 1) {
        if (threadIdx.x < s) {
            #pragma unroll
            for (int j = 0; j < 3; j++) {
                smn[threadIdx.x][j] = fminf(smn[threadIdx.x][j], smn[threadIdx.x + s][j]);
                smx[threadIdx.x][j] = fmaxf(smx[threadIdx.x][j], smx[threadIdx.x + s][j]);
            }
        }
        __syncthreads();
    }
    if (threadIdx.x == 0) {
        #pragma unroll
        for (int j = 0; j < 3; j++) { g_pmin[j] = smn[0][j]; g_pmax[j] = smx[0][j]; }
    }
}

__global__ void k_keys(const float* __restrict__ pos) {
    int idx = blockIdx.x * blockDim.x + threadIdx.x;
    if (idx >= NT) return;
    unsigned g[3];
    #pragma unroll
    for (int j = 0; j < 3; j++) {
        float denom = g_pmax[j] - g_pmin[j] + 1e-6f;
        float v = ((pos[idx * 3 + j] - g_pmin[j]) / denom) * 1023.0f;
        v = fminf(fmaxf(v, 0.0f), 1023.0f);
        g[j] = (unsigned)(int)v;
    }
    unsigned c0 = hilbert3(g[0], g[1], g[2]);
    unsigned c1 = hilbert3(g[1], g[0], g[2]);
    g_keys[idx]      = (((unsigned long long)c0) << 14) | (unsigned long long)idx;
    g_keys[NT + idx] = (((unsigned long long)c1) << 14) | (unsigned long long)idx;
}

__global__ void k_sort() {
    unsigned long long* s = (unsigned long long*)dynsmem;
    unsigned long long* keys = g_keys + blockIdx.x * NT;
    for (int i = threadIdx.x; i < NT; i += blockDim.x) s[i] = keys[i];
    __syncthreads();
    for (int k = 2; k <= NT; k <<= 1) {
        for (int j = k >> 1; j > 0; j >>= 1) {
            for (int i = threadIdx.x; i < NT; i += blockDim.x) {
                int ixj = i ^ j;
                if (ixj > i) {
                    unsigned long long a = s[i], b = s[ixj];
                    bool up = ((i & k) == 0);
                    if ((a > b) == up) { s[i] = b; s[ixj] = a; }
                }
            }
            __syncthreads();
        }
    }
    for (int i = threadIdx.x; i < NT; i += blockDim.x) keys[i] = s[i];
}

__global__ void k_order() {
    int i = blockIdx.x * blockDim.x + threadIdx.x;
    if (i >= 2 * NT) return;
    int b = i / NT;
    int idx = (int)(g_keys[i] & 0x3FFFULL);
    g_order[i] = idx;
    g_inv[b * NT + idx] = i - b * NT;
}

__global__ void k_ln256(const float* __restrict__ w, const float* __restrict__ bias) {
    int r = blockIdx.x, c = threadIdx.x;
    float v = g_q[r * DM + c];
    float mean = blockReduceSum(v) * (1.0f / DM);
    float xc = v - mean;
    float var = blockReduceSum(xc * xc) * (1.0f / DM);
    g_qn[r * DM + c] = xc * rsqrtf(var + 1e-5f) * w[c] + bias[c];
}

// ---------------- tf32x3 tensor-core GEMM: C[M,N] = A[M,K] @ B[K,N] ----------------
// M%128==0, K%32==0, N arbitrary (guarded). 256 threads, tile 128x64, k-step 32.
__global__ __launch_bounds__(256) void k_gemm_tc(int M, int N, int K,
        const float* __restrict__ A, int lda,
        const float* __restrict__ B, int ldb,
        float* __restrict__ C, int ldc) {
    float* sAhi = dynsmem;
    float* sAlo = sAhi + 32 * SA_STRIDE;
    float* sBhi = sAlo + 32 * SA_STRIDE;
    float* sBlo = sBhi + 32 * SB_STRIDE;

    int m0 = blockIdx.y * 128, n0 = blockIdx.x * 64;
    int tid = threadIdx.x;
    int wid = tid >> 5, lane = tid & 31;
    int wm = (wid & 3) * 32, wn = (wid >> 2) * 32;
    int g = lane >> 2, tg = lane & 3;

    float acc[2][4][4];
    #pragma unroll
    for (int a = 0; a < 2; a++)
        #pragma unroll
        for (int b = 0; b < 4; b++)
            #pragma unroll
            for (int c = 0; c < 4; c++) acc[a][b][c] = 0.0f;

    int am = tid >> 1, akb = (tid & 1) * 16;
    int bk = tid >> 3, bnb = (tid & 7) * 8;

    for (int k0 = 0; k0 < K; k0 += 32) {
        // load A tile 128x32 -> hi/lo transposed [k][m]
        #pragma unroll
        for (int q = 0; q < 4; q++) {
            float4 v = *(const float4*)(A + (size_t)(m0 + am) * lda + k0 + akb + q * 4);
            float xv[4] = {v.x, v.y, v.z, v.w};
            #pragma unroll
            for (int cc = 0; cc < 4; cc++) {
                unsigned hu = f2tf32(xv[cc]);
                float hf = __uint_as_float(hu);
                unsigned lu = f2tf32(xv[cc] - hf);
                int kk = akb + q * 4 + cc;
                sAhi[kk * SA_STRIDE + am] = hf;
                sAlo[kk * SA_STRIDE + am] = __uint_as_float(lu);
            }
        }
        // load B tile 32x64 -> hi/lo [k][n]
        #pragma unroll
        for (int q = 0; q < 2; q++) {
            int nn = n0 + bnb + q * 4;
            const float* Bp = B + (size_t)(k0 + bk) * ldb + nn;
            float4 v;
            if (nn + 3 < N) v = *(const float4*)Bp;
            else {
                v.x = (nn + 0 < N) ? Bp[0] : 0.0f;
                v.y = (nn + 1 < N) ? Bp[1] : 0.0f;
                v.z = (nn + 2 < N) ? Bp[2] : 0.0f;
                v.w = (nn + 3 < N) ? Bp[3] : 0.0f;
            }
            float xv[4] = {v.x, v.y, v.z, v.w};
            #pragma unroll
            for (int cc = 0; cc < 4; cc++) {
                unsigned hu = f2tf32(xv[cc]);
                float hf = __uint_as_float(hu);
                unsigned lu = f2tf32(xv[cc] - hf);
                sBhi[bk * SB_STRIDE + bnb + q * 4 + cc] = hf;
                sBlo[bk * SB_STRIDE + bnb + q * 4 + cc] = __uint_as_float(lu);
            }
        }
        __syncthreads();
        #pragma unroll
        for (int kk = 0; kk < 32; kk += 8) {
            unsigned ahi[2][4], alo[2][4], bhi[4][2], blo[4][2];
            #pragma unroll
            for (int mi = 0; mi < 2; mi++) {
                int mb = wm + mi * 16;
                ahi[mi][0] = __float_as_uint(sAhi[(kk + tg) * SA_STRIDE + mb + g]);
                ahi[mi][1] = __float_as_uint(sAhi[(kk + tg) * SA_STRIDE + mb + g + 8]);
                ahi[mi][2] = __float_as_uint(sAhi[(kk + tg + 4) * SA_STRIDE + mb + g]);
                ahi[mi][3] = __float_as_uint(sAhi[(kk + tg + 4) * SA_STRIDE + mb + g + 8]);
                alo[mi][0] = __float_as_uint(sAlo[(kk + tg) * SA_STRIDE + mb + g]);
                alo[mi][1] = __float_as_uint(sAlo[(kk + tg) * SA_STRIDE + mb + g + 8]);
                alo[mi][2] = __float_as_uint(sAlo[(kk + tg + 4) * SA_STRIDE + mb + g]);
                alo[mi][3] = __float_as_uint(sAlo[(kk + tg + 4) * SA_STRIDE + mb + g + 8]);
            }
            #pragma unroll
            for (int nj = 0; nj < 4; nj++) {
                int nb = wn + nj * 8;
                bhi[nj][0] = __float_as_uint(sBhi[(kk + tg) * SB_STRIDE + nb + g]);
                bhi[nj][1] = __float_as_uint(sBhi[(kk + tg + 4) * SB_STRIDE + nb + g]);
                blo[nj][0] = __float_as_uint(sBlo[(kk + tg) * SB_STRIDE + nb + g]);
                blo[nj][1] = __float_as_uint(sBlo[(kk + tg + 4) * SB_STRIDE + nb + g]);
            }
            #pragma unroll
            for (int mi = 0; mi < 2; mi++)
                #pragma unroll
                for (int nj = 0; nj < 4; nj++) {
                    mma_tf32(acc[mi][nj], ahi[mi], bhi[nj][0], bhi[nj][1]);
                    mma_tf32(acc[mi][nj], ahi[mi], blo[nj][0], blo[nj][1]);
                    mma_tf32(acc[mi][nj], alo[mi], bhi[nj][0], bhi[nj][1]);
                }
        }
        __syncthreads();
    }
    // epilogue
    #pragma unroll
    for (int mi = 0; mi < 2; mi++)
        #pragma unroll
        for (int nj = 0; nj < 4; nj++) {
            int row = m0 + wm + mi * 16 + g;
            int col = n0 + wn + nj * 8 + tg * 2;
            if (col + 1 < N) {
                *(float2*)(C + (size_t)row * ldc + col) =
                    make_float2(acc[mi][nj][0], acc[mi][nj][1]);
                *(float2*)(C + (size_t)(row + 8) * ldc + col) =
                    make_float2(acc[mi][nj][2], acc[mi][nj][3]);
            } else if (col < N) {
                C[(size_t)row * ldc + col] = acc[mi][nj][0];
                C[(size_t)(row + 8) * ldc + col] = acc[mi][nj][2];
            }
        }
}

// ---------------- conv + dt ----------------
__global__ void k_conv(const float* __restrict__ cw, const float* __restrict__ cb) {
    int r = blockIdx.x, b = blockIdx.y;
    __shared__ int tok[KER];
    if (threadIdx.x < KER) {
        int rr = r - (KER - 1) + threadIdx.x;
        tok[threadIdx.x] = (rr >= 0) ? g_order[b * NT + rr] : -1;
    }
    __syncthreads();
    for (int c = threadIdx.x; c < CD; c += blockDim.x) {
        float acc = cb[c];
        #pragma unroll
        for (int k = 0; k < KER; k++) {
            int t = tok[k];
            if (t >= 0) acc += cw[c * KER + k] * g_Z[(size_t)t * DP + DI + c];
        }
        float s = acc / (1.0f + __expf(-acc));
        g_XBC[(size_t)(b * NT + r) * CD + c] = s;
    }
}

__global__ void k_dt(const float* __restrict__ dtb, const float* __restrict__ alog) {
    int i = blockIdx.x * blockDim.x + threadIdx.x;
    if (i >= 2 * NT * NH) return;
    int b = i / (NT * NH);
    int rem = i - b * NT * NH;
    int r = rem / NH, h = rem - r * NH;
    int t = g_order[b * NT + r];
    float x = g_Z[(size_t)t * DP + DI + CD + h] + dtb[h];
    float sp = fmaxf(x, 0.0f) + log1pf(expf(-fabsf(x)));
    float A = -expf(alog[h]);
    g_dt[i] = sp;
    g_a[i] = sp * A;
}

// ---------------- chunked scan ----------------
// S = (w . X)^T @ B per (chunk, head, batch); register-tiled 4x4, float4 loads
__global__ __launch_bounds__(256) void k_scan1() {
    int c = blockIdx.x, h = blockIdx.y, b = blockIdx.z;
    __shared__ float sX[CQ * SR], sB[CQ * SR];
    __shared__ float scum[CQ], sw[CQ];
    int r0 = c * CQ, tid = threadIdx.x;
    for (int idx = tid; idx < CQ * 64; idx += 256) {
        int j = idx >> 6, p = idx & 63;
        sX[j * SR + p] = g_XBC[(size_t)(b * NT + r0 + j) * CD + h * HD + p];
        sB[j * SR + p] = g_XBC[(size_t)(b * NT + r0 + j) * CD + DI + p];
    }
    if (tid < CQ) scum[tid] = g_a[(size_t)(b * NT + r0 + tid) * NH + h];
    __syncthreads();
    if (tid == 0) {
        float s = 0.0f;
        for (int i = 0; i < CQ; i++) { s += scum[i]; scum[i] = s; }
    }
    __syncthreads();
    float slast = scum[CQ - 1];
    if (tid < CQ) {
        sw[tid] = __expf(slast - scum[tid]) * g_dt[(size_t)(b * NT + r0 + tid) * NH + h];
        g_cum[((b * NH + h) * NCH + c) * CQ + tid] = scum[tid];
    }
    if (tid == 0) g_cdec[(b * NH + h) * NCH + c] = __expf(slast);
    __syncthreads();
    int p0 = (tid & 15) * 4, s0 = (tid >> 4) * 4;
    float acc[4][4] = {};
    for (int j = 0; j < CQ; j++) {
        float4 xv = *(float4*)&sX[j * SR + p0];
        float4 bv = *(float4*)&sB[j * SR + s0];
        float w = sw[j];
        float wx[4] = {xv.x * w, xv.y * w, xv.z * w, xv.w * w};
        float bb[4] = {bv.x, bv.y, bv.z, bv.w};
        #pragma unroll
        for (int pi = 0; pi < 4; pi++)
            #pragma unroll
            for (int si = 0; si < 4; si++) acc[pi][si] += wx[pi] * bb[si];
    }
    size_t base = ((size_t)((b * NH + h) * NCH + c) * HD) * DS;
    #pragma unroll
    for (int pi = 0; pi < 4; pi++)
        *(float4*)&g_S[base + (size_t)(p0 + pi) * DS + s0] =
            make_float4(acc[pi][0], acc[pi][1], acc[pi][2], acc[pi][3]);
}

// inter-chunk recurrence, 64 blocks
__global__ void k_scan2() {
    int bh = blockIdx.x;
    int e = (blockIdx.y * 256 + threadIdx.x) * 4;
    float H0 = 0.f, H1 = 0.f, H2 = 0.f, H3 = 0.f;
    for (int c = 0; c < NCH; c++) {
        float cd = g_cdec[bh * NCH + c];
        size_t off = ((size_t)(bh * NCH + c)) * HD * DS + e;
        float4 s4 = *(const float4*)(g_S + off);
        *(float4*)(g_Hp + off) = make_float4(H0, H1, H2, H3);
        H0 = cd * H0 + s4.x; H1 = cd * H1 + s4.y;
        H2 = cd * H2 + s4.z; H3 = cd * H3 + s4.w;
    }
}

// per-chunk outputs; one block per (chunk, batch), loops all heads (C.B^T shared)
__global__ __launch_bounds__(256) void k_scan3(const float* __restrict__ Dv) {
    int c = blockIdx.x, b = blockIdx.y;
    int r0 = c * CQ, tid = threadIdx.x;
    float* sB  = dynsmem;             // [j][s]
    float* sC  = sB  + CQ * SR;       // [i][s]
    float* sD0 = sC  + CQ * SR;       // [i][j]
    float* sX  = sD0 + CQ * SR;       // [j][p]
    float* sH  = sX  + CQ * SR;       // [p][s]
    float* sG  = sH  + CQ * SR;       // [i][j]
    float* scum = sG + CQ * SR;
    float* sdt  = scum + CQ;
    float* seY  = sdt + CQ;

    for (int idx = tid; idx < CQ * 64; idx += 256) {
        int j = idx >> 6, s = idx & 63;
        sB[j * SR + s] = g_XBC[(size_t)(b * NT + r0 + j) * CD + DI + s];
        sC[j * SR + s] = g_XBC[(size_t)(b * NT + r0 + j) * CD + DI + DS + s];
    }
    __syncthreads();
    int i0 = (tid >> 4) * 4, j0 = (tid & 15) * 4;
    // D0 = C @ B^T
    {
        float acc[4][4] = {};
        for (int sc = 0; sc < 64; sc += 4) {
            float4 Cr[4], Br[4];
            #pragma unroll
            for (int r = 0; r < 4; r++) Cr[r] = *(float4*)&sC[(i0 + r) * SR + sc];
            #pragma unroll
            for (int q = 0; q < 4; q++) Br[q] = *(float4*)&sB[(j0 + q) * SR + sc];
            #pragma unroll
            for (int r = 0; r < 4; r++) {
                float cr[4] = {Cr[r].x, Cr[r].y, Cr[r].z, Cr[r].w};
                #pragma unroll
                for (int q = 0; q < 4; q++) {
                    acc[r][q] += cr[0] * Br[q].x + cr[1] * Br[q].y +
                                 cr[2] * Br[q].z + cr[3] * Br[q].w;
                }
            }
        }
        #pragma unroll
        for (int r = 0; r < 4; r++)
            *(float4*)&sD0[(i0 + r) * SR + j0] =
                make_float4(acc[r][0], acc[r][1], acc[r][2], acc[r][3]);
    }
    __syncthreads();

    for (int h = 0; h < NH; h++) {
        for (int idx = tid; idx < CQ * 64; idx += 256) {
            int j = idx >> 6, p = idx & 63;
            sX[j * SR + p] = g_XBC[(size_t)(b * NT + r0 + j) * CD + h * HD + p];
            sH[j * SR + p] = g_Hp[((size_t)((b * NH + h) * NCH + c) * HD) * DS + idx];
        }
        if (tid < CQ) {
            float cu = g_cum[((b * NH + h) * NCH + c) * CQ + tid];
            scum[tid] = cu;
            sdt[tid] = g_dt[(size_t)(b * NT + r0 + tid) * NH + h];
            seY[tid] = __expf(cu);
        }
        __syncthreads();
        // build G from D0
        {
            #pragma unroll
            for (int r = 0; r < 4; r++) {
                float4 d = *(float4*)&sD0[(i0 + r) * SR + j0];
                float dd[4] = {d.x, d.y, d.z, d.w};
                float gv[4];
                int i = i0 + r;
                float ci = scum[i];
                #pragma unroll
                for (int q = 0; q < 4; q++) {
                    int j = j0 + q;
                    gv[q] = (j <= i) ? __expf(ci - scum[j]) * sdt[j] * dd[q] : 0.0f;
                }
                *(float4*)&sG[(i0 + r) * SR + j0] = make_float4(gv[0], gv[1], gv[2], gv[3]);
            }
        }
        __syncthreads();
        // Y = exp(cum_i) * C@H^T + G@X + D*x
        int p0 = j0;
        float acc[4][4] = {};
        for (int sc = 0; sc < 64; sc += 4) {
            float4 Cr[4], Hc[4];
            #pragma unroll
            for (int r = 0; r < 4; r++) Cr[r] = *(float4*)&sC[(i0 + r) * SR + sc];
            #pragma unroll
            for (int q = 0; q < 4; q++) Hc[q] = *(float4*)&sH[(p0 + q) * SR + sc];
            #pragma unroll
            for (int r = 0; r < 4; r++) {
                float cr[4] = {Cr[r].x, Cr[r].y, Cr[r].z, Cr[r].w};
                #pragma unroll
                for (int q = 0; q < 4; q++) {
                    acc[r][q] += cr[0] * Hc[q].x + cr[1] * Hc[q].y +
                                 cr[2] * Hc[q].z + cr[3] * Hc[q].w;
                }
            }
        }
        #pragma unroll
        for (int r = 0; r < 4; r++) {
            float e = seY[i0 + r];
            #pragma unroll
            for (int q = 0; q < 4; q++) acc[r][q] *= e;
        }
        for (int jc = 0; jc < 64; jc += 4) {
            float G4[4][4];
            #pragma unroll
            for (int r = 0; r < 4; r++) {
                float4 t = *(float4*)&sG[(i0 + r) * SR + jc];
                G4[r][0] = t.x; G4[r][1] = t.y; G4[r][2] = t.z; G4[r][3] = t.w;
            }
            #pragma unroll
            for (int q = 0; q < 4; q++) {
                float4 xv = *(float4*)&sX[(jc + q) * SR + p0];
                float xb[4] = {xv.x, xv.y, xv.z, xv.w};
                #pragma unroll
                for (int r = 0; r < 4; r++) {
                    float gq = G4[r][q];
                    #pragma unroll
                    for (int cc = 0; cc < 4; cc++) acc[r][cc] += gq * xb[cc];
                }
            }
        }
        float Dh = Dv[h];
        #pragma unroll
        for (int r = 0; r < 4; r++) {
            float4 xi = *(float4*)&sX[(i0 + r) * SR + p0];
            float4 yv = make_float4(acc[r][0] + Dh * xi.x, acc[r][1] + Dh * xi.y,
                                    acc[r][2] + Dh * xi.z, acc[r][3] + Dh * xi.w);
            *(float4*)&g_Y[(size_t)(b * NT + r0 + i0 + r) * DI + h * HD + p0] = yv;
        }
        __syncthreads();
    }
}

// ---------------- epilogue ----------------
__global__ void k_postnorm(const float* __restrict__ nw) {
    int r = blockIdx.x, b = blockIdx.y, tid = threadIdx.x;
    int t = g_order[b * NT + r];
    float v0, v1, ss;
    {
        float y0 = g_Y[(size_t)(b * NT + r) * DI + tid];
        float g0 = g_Z[(size_t)t * DP + tid];
        v0 = y0 * (g0 / (1.0f + __expf(-g0)));
        float y1 = g_Y[(size_t)(b * NT + r) * DI + tid + 256];
        float g1 = g_Z[(size_t)t * DP + tid + 256];
        v1 = y1 * (g1 / (1.0f + __expf(-g1)));
        ss = v0 * v0 + v1 * v1;
    }
    ss = blockReduceSum(ss);
    float rr = rsqrtf(ss * (1.0f / DI) + 1e-5f);
    g_Y[(size_t)(b * NT + r) * DI + tid]       = v0 * rr * nw[tid];
    g_Y[(size_t)(b * NT + r) * DI + tid + 256] = v1 * rr * nw[tid + 256];
}

__global__ void k_combine() {
    int t = blockIdx.x, c = threadIdx.x;
    int r0 = g_inv[t], r1 = g_inv[NT + t];
    g_comb[(size_t)t * DI + c] = 0.5f * (g_Y[(size_t)r0 * DI + c] +
                                         g_Y[(size_t)(NT + r1) * DI + c]);
}

__global__ void k_final(const float* __restrict__ w, const float* __restrict__ bias,
                        float* __restrict__ dout) {
    int r = blockIdx.x, c = threadIdx.x;
    float v = g_q[r * DM + c] + g_O[r * DM + c];
    float mean = blockReduceSum(v) * (1.0f / DM);
    float xc = v - mean;
    float var = blockReduceSum(xc * xc) * (1.0f / DM);
    float res = xc * rsqrtf(var + 1e-5f) * w[c] + bias[c];
    g_q[r * DM + c] = res;
    if (dout) dout[r * DM + c] = res;
}

// ---------------- launcher ----------------
extern "C" void kernel_launch(void* const* d_in, const int* in_sizes, int n_in,
                              void* d_out, int out_size) {
    (void)in_sizes; (void)n_in; (void)out_size;
    const float* query = (const float*)d_in[0];
    const float* pos   = (const float*)d_in[1];
    const float* pre_w = (const float*)d_in[2];
    const float* pre_b = (const float*)d_in[3];
    const float* fin_w = (const float*)d_in[4];
    const float* fin_b = (const float*)d_in[5];

    const int GEMM_SMEM = (2 * 32 * SA_STRIDE + 2 * 32 * SB_STRIDE) * 4;
    const int SCAN3_SMEM = (6 * CQ * SR + 3 * CQ) * 4;
    cudaFuncSetAttribute(k_sort, cudaFuncAttributeMaxDynamicSharedMemorySize, NT * 8);
    cudaFuncSetAttribute(k_gemm_tc, cudaFuncAttributeMaxDynamicSharedMemorySize, GEMM_SMEM);
    cudaFuncSetAttribute(k_scan3, cudaFuncAttributeMaxDynamicSharedMemorySize, SCAN3_SMEM);

    float *p_qn, *p_Z, *p_comb, *p_O;
    cudaGetSymbolAddress((void**)&p_qn, g_qn);
    cudaGetSymbolAddress((void**)&p_Z, g_Z);
    cudaGetSymbolAddress((void**)&p_comb, g_comb);
    cudaGetSymbolAddress((void**)&p_O, g_O);

    k_copy<<<(NT * DM + 255) / 256, 256>>>(query);
    k_minmax<<<1, 256>>>(pos);
    k_keys<<<(NT + 255) / 256, 256>>>(pos);
    k_sort<<<2, 1024, NT * 8>>>();
    k_order<<<(2 * NT + 255) / 256, 256>>>();

    for (int L = 0; L < 2; L++) {
        const float* Win  = (const float*)d_in[6 + 8 * L];
        const float* cw   = (const float*)d_in[7 + 8 * L];
        const float* cb   = (const float*)d_in[8 + 8 * L];
        const float* dtb  = (const float*)d_in[9 + 8 * L];
        const float* alog = (const float*)d_in[10 + 8 * L];
        const float* Dv   = (const float*)d_in[11 + 8 * L];
        const float* nw   = (const float*)d_in[12 + 8 * L];
        const float* Wout = (const float*)d_in[13 + 8 * L];

        k_ln256<<<NT, 256>>>(pre_w, pre_b);
        k_gemm_tc<<<dim3((DP + 63) / 64, NT / 128), 256, GEMM_SMEM>>>(
            NT, DP, DM, p_qn, DM, Win, DP, p_Z, DP);
        k_conv<<<dim3(NT, 2), 256>>>(cw, cb);
        k_dt<<<(2 * NT * NH + 255) / 256, 256>>>(dtb, alog);
        k_scan1<<<dim3(NCH, NH, 2), 256>>>();
        k_scan2<<<dim3(16, 4), 256>>>();
        k_scan3<<<dim3(NCH, 2), 256, SCAN3_SMEM>>>(Dv);
        k_postnorm<<<dim3(NT, 2), 256>>>(nw);
        k_combine<<<NT, 512>>>();
        k_gemm_tc<<<dim3(DM / 64, NT / 128), 256, GEMM_SMEM>>>(
            NT, DM, DI, p_comb, DI, Wout, DM, p_O, DM);
        k_final<<<NT, 256>>>(fin_w, fin_b, (L == 1) ? (float*)d_out : nullptr);
    }
}

// round 4
// speedup vs baseline: 1.4359x; 1.0370x over previous
#include <cuda_runtime.h>
#include <math.h>

#define NT 16384
#define DM 256
#define DI 512
#define DS 64
#define NH 8
#define HD 64
#define CD 640      // CONV_DIM
#define DP 1160     // D_PROJ
#define KER 4
#define NCH 256     // number of chunks
#define CQ 64       // chunk length
#define SR 68       // padded row stride for 64-col smem tiles
#define SAK 36      // GEMM smem A row stride ([m][k], k=32 + pad)
#define SBN 72      // GEMM smem B row stride ([k][n], n=64 + pad)
#define NPIN 1216   // padded N for in_proj (19*64)

// ---------------- device scratch (no allocations allowed) ----------------
__device__ float g_q[NT * DM];
__device__ float g_qnhi[NT * DM];
__device__ float g_qnlo[NT * DM];
__device__ float g_Z[NT * DP];
__device__ float g_XBC[2 * NT * CD];
__device__ float g_dt[2 * NT * NH];
__device__ float g_a[2 * NT * NH];
__device__ float g_cum[2 * NH * NCH * CQ];
__device__ float g_cdec[2 * NH * NCH];
__device__ float g_S[2 * NH * NCH * HD * DS];
__device__ float g_Hp[2 * NH * NCH * HD * DS];
__device__ float g_Y[2 * NT * DI];
__device__ float g_combhi[NT * DI];
__device__ float g_comblo[NT * DI];
__device__ float g_O[NT * DM];
__device__ float g_Whi[DM * NPIN];
__device__ float g_Wlo[DM * NPIN];
__device__ unsigned long long g_keys[2 * NT];
__device__ int g_order[2 * NT];
__device__ int g_inv[2 * NT];
__device__ float g_pmin[3], g_pmax[3];

extern __shared__ float dynsmem[];

// ---------------- helpers ----------------
__device__ __forceinline__ float blockReduceSum(float v) {
    __shared__ float sh[32];
    __shared__ float tot;
    int lane = threadIdx.x & 31, wid = threadIdx.x >> 5;
    #pragma unroll
    for (int o = 16; o > 0; o >>= 1) v += __shfl_xor_sync(0xffffffffu, v, o);
    if (lane == 0) sh[wid] = v;
    __syncthreads();
    int nw = blockDim.x >> 5;
    v = (threadIdx.x < nw) ? sh[threadIdx.x] : 0.0f;
    if (wid == 0) {
        #pragma unroll
        for (int o = 16; o > 0; o >>= 1) v += __shfl_xor_sync(0xffffffffu, v, o);
        if (lane == 0) tot = v;
    }
    __syncthreads();
    return tot;
}

__device__ __forceinline__ unsigned hilbert3(unsigned a0, unsigned a1, unsigned a2) {
    unsigned x0 = a0, x1 = a1, x2 = a2;
    const unsigned M = 1u << 9;
    for (unsigned Q = M; Q > 1; Q >>= 1) {
        unsigned P = Q - 1;
        if (x0 & Q) x0 ^= P;
        {
            unsigned t = (x0 ^ x1) & P;
            if (x1 & Q) { x0 ^= P; } else { x0 ^= t; x1 ^= t; }
        }
        {
            unsigned t = (x0 ^ x2) & P;
            if (x2 & Q) { x0 ^= P; } else { x0 ^= t; x2 ^= t; }
        }
    }
    x1 ^= x0;
    x2 ^= x1;
    unsigned t = 0;
    for (unsigned Q = M; Q > 1; Q >>= 1)
        if (x2 & Q) t ^= (Q - 1);
    x0 ^= t; x1 ^= t; x2 ^= t;
    unsigned code = 0;
    for (int b = 9; b >= 0; b--) {
        code = (code << 1) | ((x0 >> b) & 1);
        code = (code << 1) | ((x1 >> b) & 1);
        code = (code << 1) | ((x2 >> b) & 1);
    }
    return code;
}

__device__ __forceinline__ unsigned f2tf32(float x) {
    unsigned u;
    asm("cvt.rna.tf32.f32 %0, %1;" : "=r"(u) : "f"(x));
    return u;
}

__device__ __forceinline__ void mma_tf32(float c[4], const unsigned a[4],
                                         unsigned b0, unsigned b1) {
    asm volatile("mma.sync.aligned.m16n8k8.row.col.f32.tf32.tf32.f32 "
        "{%0,%1,%2,%3}, {%4,%5,%6,%7}, {%8,%9}, {%0,%1,%2,%3};"
        : "+f"(c[0]), "+f"(c[1]), "+f"(c[2]), "+f"(c[3])
        : "r"(a[0]), "r"(a[1]), "r"(a[2]), "r"(a[3]), "r"(b0), "r"(b1));
}

__device__ __forceinline__ void cp16(unsigned dst, const void* src) {
    asm volatile("cp.async.cg.shared.global [%0], [%1], 16;" :: "r"(dst), "l"(src));
}

// ---------------- setup kernels ----------------
__global__ void k_copy(const float* __restrict__ src) {
    int i = blockIdx.x * blockDim.x + threadIdx.x;
    if (i < NT * DM) g_q[i] = src[i];
}

__global__ void k_minmax(const float* __restrict__ pos) {
    __shared__ float smn[256][3], smx[256][3];
    float mn[3] = {1e30f, 1e30f, 1e30f}, mx[3] = {-1e30f, -1e30f, -1e30f};
    for (int r = threadIdx.x; r < NT; r += 256) {
        #pragma unroll
        for (int j = 0; j < 3; j++) {
            float v = pos[r * 3 + j];
            mn[j] = fminf(mn[j], v);
            mx[j] = fmaxf(mx[j], v);
        }
    }
    #pragma unroll
    for (int j = 0; j < 3; j++) { smn[threadIdx.x][j] = mn[j]; smx[threadIdx.x][j] = mx[j]; }
    __syncthreads();
    for (int s = 128; s > 0; s >>= 1) {
        if (threadIdx.x < s) {
            #pragma unroll
            for (int j = 0; j < 3; j++) {
                smn[threadIdx.x][j] = fminf(smn[threadIdx.x][j], smn[threadIdx.x + s][j]);
                smx[threadIdx.x][j] = fmaxf(smx[threadIdx.x][j], smx[threadIdx.x + s][j]);
            }
        }
        __syncthreads();
    }
    if (threadIdx.x == 0) {
        #pragma unroll
        for (int j = 0; j < 3; j++) { g_pmin[j] = smn[0][j]; g_pmax[j] = smx[0][j]; }
    }
}

__global__ void k_keys(const float* __restrict__ pos) {
    int idx = blockIdx.x * blockDim.x + threadIdx.x;
    if (idx >= NT) return;
    unsigned g[3];
    #pragma unroll
    for (int j = 0; j < 3; j++) {
        float denom = g_pmax[j] - g_pmin[j] + 1e-6f;
        float v = ((pos[idx * 3 + j] - g_pmin[j]) / denom) * 1023.0f;
        v = fminf(fmaxf(v, 0.0f), 1023.0f);
        g[j] = (unsigned)(int)v;
    }
    unsigned c0 = hilbert3(g[0], g[1], g[2]);
    unsigned c1 = hilbert3(g[1], g[0], g[2]);
    g_keys[idx]      = (((unsigned long long)c0) << 14) | (unsigned long long)idx;
    g_keys[NT + idx] = (((unsigned long long)c1) << 14) | (unsigned long long)idx;
}

// padded smem index to avoid 32-way conflicts on per-thread 16-blocks
#define SADDR(i) ((i) + ((i) >> 4))

__global__ void k_sort() {
    unsigned long long* s = (unsigned long long*)dynsmem;
    unsigned long long* keys = g_keys + blockIdx.x * NT;
    int t = threadIdx.x;
    for (int i = t; i < NT; i += 1024) s[SADDR(i)] = keys[i];
    __syncthreads();

    int base = t * 16;
    unsigned long long v[16];
    // k = 2..16 entirely in registers
    #pragma unroll
    for (int r = 0; r < 16; r++) v[r] = s[SADDR(base + r)];
    #pragma unroll
    for (int k = 2; k <= 16; k <<= 1) {
        #pragma unroll
        for (int j = k >> 1; j > 0; j >>= 1) {
            #pragma unroll
            for (int r = 0; r < 16; r++) {
                int rr = r ^ j;
                if (rr > r) {
                    bool up = (((base + r) & k) == 0);
                    unsigned long long a = v[r], b = v[rr];
                    if ((a > b) == up) { v[r] = b; v[rr] = a; }
                }
            }
        }
    }
    #pragma unroll
    for (int r = 0; r < 16; r++) s[SADDR(base + r)] = v[r];
    __syncthreads();

    for (int k = 32; k <= NT; k <<= 1) {
        for (int j = k >> 1; j >= 16; j >>= 1) {
            for (int i = t; i < NT; i += 1024) {
                int ixj = i ^ j;
                if (ixj > i) {
                    unsigned long long a = s[SADDR(i)], b = s[SADDR(ixj)];
                    bool up = ((i & k) == 0);
                    if ((a > b) == up) { s[SADDR(i)] = b; s[SADDR(ixj)] = a; }
                }
            }
            __syncthreads();
        }
        // j = 8..1 in registers (i&k constant over 16-block since k>=32)
        #pragma unroll
        for (int r = 0; r < 16; r++) v[r] = s[SADDR(base + r)];
        bool up = ((base & k) == 0);
        #pragma unroll
        for (int j = 8; j > 0; j >>= 1) {
            #pragma unroll
            for (int r = 0; r < 16; r++) {
                int rr = r ^ j;
                if (rr > r) {
                    unsigned long long a = v[r], b = v[rr];
                    if ((a > b) == up) { v[r] = b; v[rr] = a; }
                }
            }
        }
        #pragma unroll
        for (int r = 0; r < 16; r++) s[SADDR(base + r)] = v[r];
        __syncthreads();
    }
    for (int i = t; i < NT; i += 1024) keys[i] = s[SADDR(i)];
}

__global__ void k_order() {
    int i = blockIdx.x * blockDim.x + threadIdx.x;
    if (i >= 2 * NT) return;
    int b = i / NT;
    int idx = (int)(g_keys[i] & 0x3FFFULL);
    g_order[i] = idx;
    g_inv[b * NT + idx] = i - b * NT;
}

__global__ void k_ln256(const float* __restrict__ w, const float* __restrict__ bias) {
    int r = blockIdx.x, c = threadIdx.x;
    float v = g_q[r * DM + c];
    float mean = blockReduceSum(v) * (1.0f / DM);
    float xc = v - mean;
    float var = blockReduceSum(xc * xc) * (1.0f / DM);
    float res = xc * rsqrtf(var + 1e-5f) * w[c] + bias[c];
    unsigned hu = f2tf32(res);
    float hf = __uint_as_float(hu);
    g_qnhi[r * DM + c] = hf;
    g_qnlo[r * DM + c] = __uint_as_float(f2tf32(res - hf));
}

__global__ void k_splitW(const float* __restrict__ src, int K, int N, int NP) {
    int idx = blockIdx.x * blockDim.x + threadIdx.x;
    if (idx >= K * NP) return;
    int k = idx / NP, n = idx - k * NP;
    float v = (n < N) ? src[k * N + n] : 0.0f;
    unsigned hu = f2tf32(v);
    float hf = __uint_as_float(hu);
    g_Whi[idx] = hf;
    g_Wlo[idx] = __uint_as_float(f2tf32(v - hf));
}

// ---------------- double-buffered cp.async tf32x3 GEMM ----------------
// C[M,N] = A[M,K] @ B[K,N]; A pre-split hi/lo [M,K]; B pre-split hi/lo [K,NP].
// Tile 128x64, k-step 32, 256 threads, 2-stage cp.async pipeline.
__device__ __forceinline__ void gemm_load_stage(
    const float* __restrict__ Ahi, const float* __restrict__ Alo, int lda,
    const float* __restrict__ Bhi, const float* __restrict__ Blo, int ldb,
    int m0, int n0, int kt, float* sA0, float* sA1, float* sB0, float* sB1,
    int tid) {
    int k0 = kt * 32;
    int r = tid >> 1, c0 = (tid & 1) * 16;
    const float* pah = Ahi + (size_t)(m0 + r) * lda + k0 + c0;
    const float* pal = Alo + (size_t)(m0 + r) * lda + k0 + c0;
    unsigned dah = (unsigned)__cvta_generic_to_shared(sA0 + r * SAK + c0);
    unsigned dal = (unsigned)__cvta_generic_to_shared(sA1 + r * SAK + c0);
    #pragma unroll
    for (int q = 0; q < 4; q++) {
        cp16(dah + q * 16, pah + q * 4);
        cp16(dal + q * 16, pal + q * 4);
    }
    int kr = tid >> 3, cb = (tid & 7) * 8;
    const float* pbh = Bhi + (size_t)(k0 + kr) * ldb + n0 + cb;
    const float* pbl = Blo + (size_t)(k0 + kr) * ldb + n0 + cb;
    unsigned dbh = (unsigned)__cvta_generic_to_shared(sB0 + kr * SBN + cb);
    unsigned dbl = (unsigned)__cvta_generic_to_shared(sB1 + kr * SBN + cb);
    #pragma unroll
    for (int q = 0; q < 2; q++) {
        cp16(dbh + q * 16, pbh + q * 4);
        cp16(dbl + q * 16, pbl + q * 4);
    }
}

__global__ __launch_bounds__(256) void k_gemm_tc2(int M, int N, int K, int ldb,
        const float* __restrict__ Ahi, const float* __restrict__ Alo, int lda,
        float* __restrict__ C, int ldc) {
    const float* Bhi = g_Whi;
    const float* Blo = g_Wlo;
    // smem: A[2 stages][2 hl][128*SAK], B[2][2][32*SBN]
    float* sA = dynsmem;                       // 4 * 128*SAK
    float* sB = sA + 4 * 128 * SAK;            // 4 * 32*SBN

    int m0 = blockIdx.y * 128, n0 = blockIdx.x * 64;
    int tid = threadIdx.x;
    int wid = tid >> 5, lane = tid & 31;
    int wm = (wid & 3) * 32, wn = (wid >> 2) * 32;
    int g = lane >> 2, tg = lane & 3;
    int KT = K / 32;

    float acc[2][4][4];
    #pragma unroll
    for (int a = 0; a < 2; a++)
        #pragma unroll
        for (int b = 0; b < 4; b++)
            #pragma unroll
            for (int c = 0; c < 4; c++) acc[a][b][c] = 0.0f;

    gemm_load_stage(Ahi, Alo, lda, Bhi, Blo, ldb, m0, n0, 0,
                    sA, sA + 128 * SAK, sB, sB + 32 * SBN, tid);
    asm volatile("cp.async.commit_group;");

    for (int kt = 0; kt < KT; kt++) {
        int st = kt & 1;
        if (kt + 1 < KT) {
            int ns = st ^ 1;
            gemm_load_stage(Ahi, Alo, lda, Bhi, Blo, ldb, m0, n0, kt + 1,
                            sA + (2 * ns) * 128 * SAK, sA + (2 * ns + 1) * 128 * SAK,
                            sB + (2 * ns) * 32 * SBN, sB + (2 * ns + 1) * 32 * SBN, tid);
            asm volatile("cp.async.commit_group;");
            asm volatile("cp.async.wait_group 1;");
        } else {
            asm volatile("cp.async.wait_group 0;");
        }
        __syncthreads();
        float* sAhi = sA + (2 * st) * 128 * SAK;
        float* sAlo = sAhi + 128 * SAK;
        float* sBhi = sB + (2 * st) * 32 * SBN;
        float* sBlo = sBhi + 32 * SBN;
        #pragma unroll
        for (int kk = 0; kk < 32; kk += 8) {
            unsigned ahi[2][4], alo[2][4], bhi[4][2], blo[4][2];
            #pragma unroll
            for (int mi = 0; mi < 2; mi++) {
                int mb = wm + mi * 16;
                ahi[mi][0] = __float_as_uint(sAhi[(mb + g) * SAK + kk + tg]);
                ahi[mi][1] = __float_as_uint(sAhi[(mb + g + 8) * SAK + kk + tg]);
                ahi[mi][2] = __float_as_uint(sAhi[(mb + g) * SAK + kk + tg + 4]);
                ahi[mi][3] = __float_as_uint(sAhi[(mb + g + 8) * SAK + kk + tg + 4]);
                alo[mi][0] = __float_as_uint(sAlo[(mb + g) * SAK + kk + tg]);
                alo[mi][1] = __float_as_uint(sAlo[(mb + g + 8) * SAK + kk + tg]);
                alo[mi][2] = __float_as_uint(sAlo[(mb + g) * SAK + kk + tg + 4]);
                alo[mi][3] = __float_as_uint(sAlo[(mb + g + 8) * SAK + kk + tg + 4]);
            }
            #pragma unroll
            for (int nj = 0; nj < 4; nj++) {
                int nb = wn + nj * 8;
                bhi[nj][0] = __float_as_uint(sBhi[(kk + tg) * SBN + nb + g]);
                bhi[nj][1] = __float_as_uint(sBhi[(kk + tg + 4) * SBN + nb + g]);
                blo[nj][0] = __float_as_uint(sBlo[(kk + tg) * SBN + nb + g]);
                blo[nj][1] = __float_as_uint(sBlo[(kk + tg + 4) * SBN + nb + g]);
            }
            #pragma unroll
            for (int mi = 0; mi < 2; mi++)
                #pragma unroll
                for (int nj = 0; nj < 4; nj++) {
                    mma_tf32(acc[mi][nj], ahi[mi], bhi[nj][0], bhi[nj][1]);
                    mma_tf32(acc[mi][nj], ahi[mi], blo[nj][0], blo[nj][1]);
                    mma_tf32(acc[mi][nj], alo[mi], bhi[nj][0], bhi[nj][1]);
                }
        }
        __syncthreads();
    }
    #pragma unroll
    for (int mi = 0; mi < 2; mi++)
        #pragma unroll
        for (int nj = 0; nj < 4; nj++) {
            int row = m0 + wm + mi * 16 + g;
            int col = n0 + wn + nj * 8 + tg * 2;
            if (col + 1 < N) {
                *(float2*)(C + (size_t)row * ldc + col) =
                    make_float2(acc[mi][nj][0], acc[mi][nj][1]);
                *(float2*)(C + (size_t)(row + 8) * ldc + col) =
                    make_float2(acc[mi][nj][2], acc[mi][nj][3]);
            } else if (col < N) {
                C[(size_t)row * ldc + col] = acc[mi][nj][0];
                C[(size_t)(row + 8) * ldc + col] = acc[mi][nj][2];
            }
        }
}

// ---------------- conv + dt ----------------
__global__ void k_conv(const float* __restrict__ cw, const float* __restrict__ cb) {
    int r = blockIdx.x, b = blockIdx.y;
    __shared__ int tok[KER];
    if (threadIdx.x < KER) {
        int rr = r - (KER - 1) + threadIdx.x;
        tok[threadIdx.x] = (rr >= 0) ? g_order[b * NT + rr] : -1;
    }
    __syncthreads();
    for (int c = threadIdx.x; c < CD; c += blockDim.x) {
        float acc = cb[c];
        #pragma unroll
        for (int k = 0; k < KER; k++) {
            int t = tok[k];
            if (t >= 0) acc += cw[c * KER + k] * g_Z[(size_t)t * DP + DI + c];
        }
        float s = acc / (1.0f + __expf(-acc));
        g_XBC[(size_t)(b * NT + r) * CD + c] = s;
    }
}

__global__ void k_dt(const float* __restrict__ dtb, const float* __restrict__ alog) {
    int i = blockIdx.x * blockDim.x + threadIdx.x;
    if (i >= 2 * NT * NH) return;
    int b = i / (NT * NH);
    int rem = i - b * NT * NH;
    int r = rem / NH, h = rem - r * NH;
    int t = g_order[b * NT + r];
    float x = g_Z[(size_t)t * DP + DI + CD + h] + dtb[h];
    float sp = fmaxf(x, 0.0f) + log1pf(expf(-fabsf(x)));
    float A = -expf(alog[h]);
    g_dt[i] = sp;
    g_a[i] = sp * A;
}

// ---------------- chunked scan ----------------
__global__ __launch_bounds__(256) void k_scan1() {
    int c = blockIdx.x, h = blockIdx.y, b = blockIdx.z;
    __shared__ float sX[CQ * SR], sB[CQ * SR];
    __shared__ float scum[CQ], sw[CQ];
    int r0 = c * CQ, tid = threadIdx.x;
    for (int idx = tid; idx < CQ * 64; idx += 256) {
        int j = idx >> 6, p = idx & 63;
        sX[j * SR + p] = g_XBC[(size_t)(b * NT + r0 + j) * CD + h * HD + p];
        sB[j * SR + p] = g_XBC[(size_t)(b * NT + r0 + j) * CD + DI + p];
    }
    if (tid < CQ) scum[tid] = g_a[(size_t)(b * NT + r0 + tid) * NH + h];
    __syncthreads();
    if (tid == 0) {
        float s = 0.0f;
        for (int i = 0; i < CQ; i++) { s += scum[i]; scum[i] = s; }
    }
    __syncthreads();
    float slast = scum[CQ - 1];
    if (tid < CQ) {
        sw[tid] = __expf(slast - scum[tid]) * g_dt[(size_t)(b * NT + r0 + tid) * NH + h];
        g_cum[((b * NH + h) * NCH + c) * CQ + tid] = scum[tid];
    }
    if (tid == 0) g_cdec[(b * NH + h) * NCH + c] = __expf(slast);
    __syncthreads();
    int p0 = (tid & 15) * 4, s0 = (tid >> 4) * 4;
    float acc[4][4] = {};
    for (int j = 0; j < CQ; j++) {
        float4 xv = *(float4*)&sX[j * SR + p0];
        float4 bv = *(float4*)&sB[j * SR + s0];
        float w = sw[j];
        float wx[4] = {xv.x * w, xv.y * w, xv.z * w, xv.w * w};
        float bb[4] = {bv.x, bv.y, bv.z, bv.w};
        #pragma unroll
        for (int pi = 0; pi < 4; pi++)
            #pragma unroll
            for (int si = 0; si < 4; si++) acc[pi][si] += wx[pi] * bb[si];
    }
    size_t base = ((size_t)((b * NH + h) * NCH + c) * HD) * DS;
    #pragma unroll
    for (int pi = 0; pi < 4; pi++)
        *(float4*)&g_S[base + (size_t)(p0 + pi) * DS + s0] =
            make_float4(acc[pi][0], acc[pi][1], acc[pi][2], acc[pi][3]);
}

// inter-chunk recurrence: 256 blocks x 256 threads, 1 lane per state element
__global__ void k_scan2() {
    __shared__ float scd[NCH];
    int bh = blockIdx.x >> 4;
    int e = ((blockIdx.x & 15) << 8) + threadIdx.x;
    if (threadIdx.x < NCH) scd[threadIdx.x] = g_cdec[bh * NCH + threadIdx.x];
    __syncthreads();
    float H = 0.0f;
    for (int c = 0; c < NCH; c++) {
        size_t off = ((size_t)(bh * NCH + c)) * (HD * DS) + e;
        float s = g_S[off];
        g_Hp[off] = H;
        H = scd[c] * H + s;
    }
}

// per-chunk outputs; one block per (chunk, batch), loops all heads
__global__ __launch_bounds__(256) void k_scan3(const float* __restrict__ Dv) {
    int c = blockIdx.x, b = blockIdx.y;
    int r0 = c * CQ, tid = threadIdx.x;
    float* sB  = dynsmem;
    float* sC  = sB  + CQ * SR;
    float* sD0 = sC  + CQ * SR;
    float* sX  = sD0 + CQ * SR;
    float* sH  = sX  + CQ * SR;
    float* sG  = sH  + CQ * SR;
    float* scum = sG + CQ * SR;
    float* sdt  = scum + CQ;
    float* seY  = sdt + CQ;

    for (int idx = tid; idx < CQ * 64; idx += 256) {
        int j = idx >> 6, s = idx & 63;
        sB[j * SR + s] = g_XBC[(size_t)(b * NT + r0 + j) * CD + DI + s];
        sC[j * SR + s] = g_XBC[(size_t)(b * NT + r0 + j) * CD + DI + DS + s];
    }
    __syncthreads();
    int i0 = (tid >> 4) * 4, j0 = (tid & 15) * 4;
    {
        float acc[4][4] = {};
        for (int sc = 0; sc < 64; sc += 4) {
            float4 Cr[4], Br[4];
            #pragma unroll
            for (int r = 0; r < 4; r++) Cr[r] = *(float4*)&sC[(i0 + r) * SR + sc];
            #pragma unroll
            for (int q = 0; q < 4; q++) Br[q] = *(float4*)&sB[(j0 + q) * SR + sc];
            #pragma unroll
            for (int r = 0; r < 4; r++) {
                float cr[4] = {Cr[r].x, Cr[r].y, Cr[r].z, Cr[r].w};
                #pragma unroll
                for (int q = 0; q < 4; q++) {
                    acc[r][q] += cr[0] * Br[q].x + cr[1] * Br[q].y +
                                 cr[2] * Br[q].z + cr[3] * Br[q].w;
                }
            }
        }
        #pragma unroll
        for (int r = 0; r < 4; r++)
            *(float4*)&sD0[(i0 + r) * SR + j0] =
                make_float4(acc[r][0], acc[r][1], acc[r][2], acc[r][3]);
    }
    __syncthreads();

    for (int h = 0; h < NH; h++) {
        for (int idx = tid; idx < CQ * 64; idx += 256) {
            int j = idx >> 6, p = idx & 63;
            sX[j * SR + p] = g_XBC[(size_t)(b * NT + r0 + j) * CD + h * HD + p];
            sH[j * SR + p] = g_Hp[((size_t)((b * NH + h) * NCH + c) * HD) * DS + idx];
        }
        if (tid < CQ) {
            float cu = g_cum[((b * NH + h) * NCH + c) * CQ + tid];
            scum[tid] = cu;
            sdt[tid] = g_dt[(size_t)(b * NT + r0 + tid) * NH + h];
            seY[tid] = __expf(cu);
        }
        __syncthreads();
        {
            #pragma unroll
            for (int r = 0; r < 4; r++) {
                float4 d = *(float4*)&sD0[(i0 + r) * SR + j0];
                float dd[4] = {d.x, d.y, d.z, d.w};
                float gv[4];
                int i = i0 + r;
                float ci = scum[i];
                #pragma unroll
                for (int q = 0; q < 4; q++) {
                    int j = j0 + q;
                    gv[q] = (j <= i) ? __expf(ci - scum[j]) * sdt[j] * dd[q] : 0.0f;
                }
                *(float4*)&sG[(i0 + r) * SR + j0] = make_float4(gv[0], gv[1], gv[2], gv[3]);
            }
        }
        __syncthreads();
        int p0 = j0;
        float acc[4][4] = {};
        for (int sc = 0; sc < 64; sc += 4) {
            float4 Cr[4], Hc[4];
            #pragma unroll
            for (int r = 0; r < 4; r++) Cr[r] = *(float4*)&sC[(i0 + r) * SR + sc];
            #pragma unroll
            for (int q = 0; q < 4; q++) Hc[q] = *(float4*)&sH[(p0 + q) * SR + sc];
            #pragma unroll
            for (int r = 0; r < 4; r++) {
                float cr[4] = {Cr[r].x, Cr[r].y, Cr[r].z, Cr[r].w};
                #pragma unroll
                for (int q = 0; q < 4; q++) {
                    acc[r][q] += cr[0] * Hc[q].x + cr[1] * Hc[q].y +
                                 cr[2] * Hc[q].z + cr[3] * Hc[q].w;
                }
            }
        }
        #pragma unroll
        for (int r = 0; r < 4; r++) {
            float e = seY[i0 + r];
            #pragma unroll
            for (int q = 0; q < 4; q++) acc[r][q] *= e;
        }
        for (int jc = 0; jc < 64; jc += 4) {
            float G4[4][4];
            #pragma unroll
            for (int r = 0; r < 4; r++) {
                float4 t = *(float4*)&sG[(i0 + r) * SR + jc];
                G4[r][0] = t.x; G4[r][1] = t.y; G4[r][2] = t.z; G4[r][3] = t.w;
            }
            #pragma unroll
            for (int q = 0; q < 4; q++) {
                float4 xv = *(float4*)&sX[(jc + q) * SR + p0];
                float xb[4] = {xv.x, xv.y, xv.z, xv.w};
                #pragma unroll
                for (int r = 0; r < 4; r++) {
                    float gq = G4[r][q];
                    #pragma unroll
                    for (int cc = 0; cc < 4; cc++) acc[r][cc] += gq * xb[cc];
                }
            }
        }
        float Dh = Dv[h];
        #pragma unroll
        for (int r = 0; r < 4; r++) {
            float4 xi = *(float4*)&sX[(i0 + r) * SR + p0];
            float4 yv = make_float4(acc[r][0] + Dh * xi.x, acc[r][1] + Dh * xi.y,
                                    acc[r][2] + Dh * xi.z, acc[r][3] + Dh * xi.w);
            *(float4*)&g_Y[(size_t)(b * NT + r0 + i0 + r) * DI + h * HD + p0] = yv;
        }
        __syncthreads();
    }
}

// ---------------- epilogue ----------------
__global__ void k_postnorm(const float* __restrict__ nw) {
    int r = blockIdx.x, b = blockIdx.y, tid = threadIdx.x;
    int t = g_order[b * NT + r];
    float v0, v1, ss;
    {
        float y0 = g_Y[(size_t)(b * NT + r) * DI + tid];
        float g0 = g_Z[(size_t)t * DP + tid];
        v0 = y0 * (g0 / (1.0f + __expf(-g0)));
        float y1 = g_Y[(size_t)(b * NT + r) * DI + tid + 256];
        float g1 = g_Z[(size_t)t * DP + tid + 256];
        v1 = y1 * (g1 / (1.0f + __expf(-g1)));
        ss = v0 * v0 + v1 * v1;
    }
    ss = blockReduceSum(ss);
    float rr = rsqrtf(ss * (1.0f / DI) + 1e-5f);
    g_Y[(size_t)(b * NT + r) * DI + tid]       = v0 * rr * nw[tid];
    g_Y[(size_t)(b * NT + r) * DI + tid + 256] = v1 * rr * nw[tid + 256];
}

__global__ void k_combine() {
    int t = blockIdx.x, c = threadIdx.x;
    int r0 = g_inv[t], r1 = g_inv[NT + t];
    float v = 0.5f * (g_Y[(size_t)r0 * DI + c] + g_Y[(size_t)(NT + r1) * DI + c]);
    unsigned hu = f2tf32(v);
    float hf = __uint_as_float(hu);
    g_combhi[(size_t)t * DI + c] = hf;
    g_comblo[(size_t)t * DI + c] = __uint_as_float(f2tf32(v - hf));
}

__global__ void k_final(const float* __restrict__ w, const float* __restrict__ bias,
                        float* __restrict__ dout) {
    int r = blockIdx.x, c = threadIdx.x;
    float v = g_q[r * DM + c] + g_O[r * DM + c];
    float mean = blockReduceSum(v) * (1.0f / DM);
    float xc = v - mean;
    float var = blockReduceSum(xc * xc) * (1.0f / DM);
    float res = xc * rsqrtf(var + 1e-5f) * w[c] + bias[c];
    g_q[r * DM + c] = res;
    if (dout) dout[r * DM + c] = res;
}

// ---------------- launcher ----------------
extern "C" void kernel_launch(void* const* d_in, const int* in_sizes, int n_in,
                              void* d_out, int out_size) {
    (void)in_sizes; (void)n_in; (void)out_size;
    const float* query = (const float*)d_in[0];
    const float* pos   = (const float*)d_in[1];
    const float* pre_w = (const float*)d_in[2];
    const float* pre_b = (const float*)d_in[3];
    const float* fin_w = (const float*)d_in[4];
    const float* fin_b = (const float*)d_in[5];

    const int SORT_SMEM = (NT + NT / 16) * 8;
    const int GEMM_SMEM = (4 * 128 * SAK + 4 * 32 * SBN) * 4;
    const int SCAN3_SMEM = (6 * CQ * SR + 3 * CQ) * 4;
    cudaFuncSetAttribute(k_sort, cudaFuncAttributeMaxDynamicSharedMemorySize, SORT_SMEM);
    cudaFuncSetAttribute(k_gemm_tc2, cudaFuncAttributeMaxDynamicSharedMemorySize, GEMM_SMEM);
    cudaFuncSetAttribute(k_scan3, cudaFuncAttributeMaxDynamicSharedMemorySize, SCAN3_SMEM);

    float *p_qnhi, *p_qnlo, *p_combhi, *p_comblo, *p_Z, *p_O;
    cudaGetSymbolAddress((void**)&p_qnhi, g_qnhi);
    cudaGetSymbolAddress((void**)&p_qnlo, g_qnlo);
    cudaGetSymbolAddress((void**)&p_combhi, g_combhi);
    cudaGetSymbolAddress((void**)&p_comblo, g_comblo);
    cudaGetSymbolAddress((void**)&p_Z, g_Z);
    cudaGetSymbolAddress((void**)&p_O, g_O);

    k_copy<<<(NT * DM + 255) / 256, 256>>>(query);
    k_minmax<<<1, 256>>>(pos);
    k_keys<<<(NT + 255) / 256, 256>>>(pos);
    k_sort<<<2, 1024, SORT_SMEM>>>();
    k_order<<<(2 * NT + 255) / 256, 256>>>();

    for (int L = 0; L < 2; L++) {
        const float* Win  = (const float*)d_in[6 + 8 * L];
        const float* cw   = (const float*)d_in[7 + 8 * L];
        const float* cb   = (const float*)d_in[8 + 8 * L];
        const float* dtb  = (const float*)d_in[9 + 8 * L];
        const float* alog = (const float*)d_in[10 + 8 * L];
        const float* Dv   = (const float*)d_in[11 + 8 * L];
        const float* nw   = (const float*)d_in[12 + 8 * L];
        const float* Wout = (const float*)d_in[13 + 8 * L];

        k_ln256<<<NT, 256>>>(pre_w, pre_b);
        k_splitW<<<(DM * NPIN + 255) / 256, 256>>>(Win, DM, DP, NPIN);
        k_gemm_tc2<<<dim3(NPIN / 64, NT / 128), 256, GEMM_SMEM>>>(
            NT, DP, DM, NPIN, p_qnhi, p_qnlo, DM, p_Z, DP);
        k_conv<<<dim3(NT, 2), 256>>>(cw, cb);
        k_dt<<<(2 * NT * NH + 255) / 256, 256>>>(dtb, alog);
        k_scan1<<<dim3(NCH, NH, 2), 256>>>();
        k_scan2<<<256, 256>>>();
        k_scan3<<<dim3(NCH, 2), 256, SCAN3_SMEM>>>(Dv);
        k_postnorm<<<dim3(NT, 2), 256>>>(nw);
        k_combine<<<NT, 512>>>();
        k_splitW<<<(DI * DM + 255) / 256, 256>>>(Wout, DI, DM, DM);
        k_gemm_tc2<<<dim3(DM / 64, NT / 128), 256, GEMM_SMEM>>>(
            NT, DM, DI, DM, p_combhi, p_comblo, DI, p_O, DM);
        k_final<<<NT, 256>>>(fin_w, fin_b, (L == 1) ? (float*)d_out : nullptr);
    }
}

// round 5
// speedup vs baseline: 1.7451x; 1.2153x over previous
#include <cuda_runtime.h>
#include <cuda_bf16.h>
#include <math.h>

#define NT 16384
#define DM 256
#define DI 512
#define DS 64
#define NH 8
#define HD 64
#define CD 640      // CONV_DIM
#define DP 1160     // D_PROJ
#define KER 4
#define NCH 256     // number of chunks
#define CQ 64       // chunk length
#define SR 68       // padded row stride for 64-col smem tiles
#define NPIN 1216   // padded N for in_proj (19*64)
#define WSTR 20     // GEMM smem row stride in uints (conflict-free for frag loads)

// ---------------- device scratch (no allocations allowed) ----------------
__device__ float g_q[NT * DM];
__device__ unsigned g_qnhi[NT * (DM / 2)];
__device__ unsigned g_qnlo[NT * (DM / 2)];
__device__ float g_Z[NT * DP];
__device__ float g_XBC[2 * NT * CD];
__device__ float g_dt[2 * NT * NH];
__device__ float g_a[2 * NT * NH];
__device__ float g_cum[2 * NH * NCH * CQ];
__device__ float g_cdec[2 * NH * NCH];
__device__ float g_S[2 * NH * NCH * HD * DS];
__device__ float g_Hp[2 * NH * NCH * HD * DS];
__device__ float g_Y[2 * NT * DI];
__device__ unsigned g_combhi[NT * (DI / 2)];
__device__ unsigned g_comblo[NT * (DI / 2)];
__device__ float g_O[NT * DM];
__device__ unsigned g_Whi[NPIN * (DM / 2)];   // transposed packed weights [n][k/2]
__device__ unsigned g_Wlo[NPIN * (DM / 2)];
__device__ unsigned long long g_keys[2 * NT];
__device__ int g_order[2 * NT];
__device__ int g_inv[2 * NT];
__device__ float g_pmin[3], g_pmax[3];

extern __shared__ float dynsmem[];

// ---------------- helpers ----------------
__device__ __forceinline__ float blockReduceSum(float v) {
    __shared__ float sh[32];
    __shared__ float tot;
    int lane = threadIdx.x & 31, wid = threadIdx.x >> 5;
    #pragma unroll
    for (int o = 16; o > 0; o >>= 1) v += __shfl_xor_sync(0xffffffffu, v, o);
    if (lane == 0) sh[wid] = v;
    __syncthreads();
    int nw = blockDim.x >> 5;
    v = (threadIdx.x < nw) ? sh[threadIdx.x] : 0.0f;
    if (wid == 0) {
        #pragma unroll
        for (int o = 16; o > 0; o >>= 1) v += __shfl_xor_sync(0xffffffffu, v, o);
        if (lane == 0) tot = v;
    }
    __syncthreads();
    return tot;
}

__device__ __forceinline__ unsigned hilbert3(unsigned a0, unsigned a1, unsigned a2) {
    unsigned x0 = a0, x1 = a1, x2 = a2;
    const unsigned M = 1u << 9;
    for (unsigned Q = M; Q > 1; Q >>= 1) {
        unsigned P = Q - 1;
        if (x0 & Q) x0 ^= P;
        {
            unsigned t = (x0 ^ x1) & P;
            if (x1 & Q) { x0 ^= P; } else { x0 ^= t; x1 ^= t; }
        }
        {
            unsigned t = (x0 ^ x2) & P;
            if (x2 & Q) { x0 ^= P; } else { x0 ^= t; x2 ^= t; }
        }
    }
    x1 ^= x0;
    x2 ^= x1;
    unsigned t = 0;
    for (unsigned Q = M; Q > 1; Q >>= 1)
        if (x2 & Q) t ^= (Q - 1);
    x0 ^= t; x1 ^= t; x2 ^= t;
    unsigned code = 0;
    for (int b = 9; b >= 0; b--) {
        code = (code << 1) | ((x0 >> b) & 1);
        code = (code << 1) | ((x1 >> b) & 1);
        code = (code << 1) | ((x2 >> b) & 1);
    }
    return code;
}

__device__ __forceinline__ void bfsplit(float x, unsigned short& hi, unsigned short& lo) {
    __nv_bfloat16 h = __float2bfloat16(x);
    __nv_bfloat16 l = __float2bfloat16(x - __bfloat162float(h));
    hi = *(unsigned short*)&h;
    lo = *(unsigned short*)&l;
}

__device__ __forceinline__ void mma_bf16(float c[4], const unsigned a[4],
                                         unsigned b0, unsigned b1) {
    asm volatile("mma.sync.aligned.m16n8k16.row.col.f32.bf16.bf16.f32 "
        "{%0,%1,%2,%3}, {%4,%5,%6,%7}, {%8,%9}, {%0,%1,%2,%3};"
        : "+f"(c[0]), "+f"(c[1]), "+f"(c[2]), "+f"(c[3])
        : "r"(a[0]), "r"(a[1]), "r"(a[2]), "r"(a[3]), "r"(b0), "r"(b1));
}

__device__ __forceinline__ void cp16(unsigned dst, const void* src) {
    asm volatile("cp.async.cg.shared.global [%0], [%1], 16;" :: "r"(dst), "l"(src));
}

// ---------------- setup kernels ----------------
__global__ void k_copy(const float* __restrict__ src) {
    int i = blockIdx.x * blockDim.x + threadIdx.x;
    if (i < NT * DM) g_q[i] = src[i];
}

__global__ void k_minmax(const float* __restrict__ pos) {
    __shared__ float smn[256][3], smx[256][3];
    float mn[3] = {1e30f, 1e30f, 1e30f}, mx[3] = {-1e30f, -1e30f, -1e30f};
    for (int r = threadIdx.x; r < NT; r += 256) {
        #pragma unroll
        for (int j = 0; j < 3; j++) {
            float v = pos[r * 3 + j];
            mn[j] = fminf(mn[j], v);
            mx[j] = fmaxf(mx[j], v);
        }
    }
    #pragma unroll
    for (int j = 0; j < 3; j++) { smn[threadIdx.x][j] = mn[j]; smx[threadIdx.x][j] = mx[j]; }
    __syncthreads();
    for (int s = 128; s > 0; s >>= 1) {
        if (threadIdx.x < s) {
            #pragma unroll
            for (int j = 0; j < 3; j++) {
                smn[threadIdx.x][j] = fminf(smn[threadIdx.x][j], smn[threadIdx.x + s][j]);
                smx[threadIdx.x][j] = fmaxf(smx[threadIdx.x][j], smx[threadIdx.x + s][j]);
            }
        }
        __syncthreads();
    }
    if (threadIdx.x == 0) {
        #pragma unroll
        for (int j = 0; j < 3; j++) { g_pmin[j] = smn[0][j]; g_pmax[j] = smx[0][j]; }
    }
}

__global__ void k_keys(const float* __restrict__ pos) {
    int idx = blockIdx.x * blockDim.x + threadIdx.x;
    if (idx >= NT) return;
    unsigned g[3];
    #pragma unroll
    for (int j = 0; j < 3; j++) {
        float denom = g_pmax[j] - g_pmin[j] + 1e-6f;
        float v = ((pos[idx * 3 + j] - g_pmin[j]) / denom) * 1023.0f;
        v = fminf(fmaxf(v, 0.0f), 1023.0f);
        g[j] = (unsigned)(int)v;
    }
    unsigned c0 = hilbert3(g[0], g[1], g[2]);
    unsigned c1 = hilbert3(g[1], g[0], g[2]);
    g_keys[idx]      = (((unsigned long long)c0) << 14) | (unsigned long long)idx;
    g_keys[NT + idx] = (((unsigned long long)c1) << 14) | (unsigned long long)idx;
}

#define SADDR(i) ((i) + ((i) >> 4))

__global__ void k_sort() {
    unsigned long long* s = (unsigned long long*)dynsmem;
    unsigned long long* keys = g_keys + blockIdx.x * NT;
    int t = threadIdx.x;
    for (int i = t; i < NT; i += 1024) s[SADDR(i)] = keys[i];
    __syncthreads();

    int base = t * 16;
    unsigned long long v[16];
    #pragma unroll
    for (int r = 0; r < 16; r++) v[r] = s[SADDR(base + r)];
    #pragma unroll
    for (int k = 2; k <= 16; k <<= 1) {
        #pragma unroll
        for (int j = k >> 1; j > 0; j >>= 1) {
            #pragma unroll
            for (int r = 0; r < 16; r++) {
                int rr = r ^ j;
                if (rr > r) {
                    bool up = (((base + r) & k) == 0);
                    unsigned long long a = v[r], b = v[rr];
                    if ((a > b) == up) { v[r] = b; v[rr] = a; }
                }
            }
        }
    }
    #pragma unroll
    for (int r = 0; r < 16; r++) s[SADDR(base + r)] = v[r];
    __syncthreads();

    for (int k = 32; k <= NT; k <<= 1) {
        for (int j = k >> 1; j >= 16; j >>= 1) {
            for (int i = t; i < NT; i += 1024) {
                int ixj = i ^ j;
                if (ixj > i) {
                    unsigned long long a = s[SADDR(i)], b = s[SADDR(ixj)];
                    bool up = ((i & k) == 0);
                    if ((a > b) == up) { s[SADDR(i)] = b; s[SADDR(ixj)] = a; }
                }
            }
            __syncthreads();
        }
        #pragma unroll
        for (int r = 0; r < 16; r++) v[r] = s[SADDR(base + r)];
        bool up = ((base & k) == 0);
        #pragma unroll
        for (int j = 8; j > 0; j >>= 1) {
            #pragma unroll
            for (int r = 0; r < 16; r++) {
                int rr = r ^ j;
                if (rr > r) {
                    unsigned long long a = v[r], b = v[rr];
                    if ((a > b) == up) { v[r] = b; v[rr] = a; }
                }
            }
        }
        #pragma unroll
        for (int r = 0; r < 16; r++) s[SADDR(base + r)] = v[r];
        __syncthreads();
    }
    for (int i = t; i < NT; i += 1024) keys[i] = s[SADDR(i)];
}

__global__ void k_order() {
    int i = blockIdx.x * blockDim.x + threadIdx.x;
    if (i >= 2 * NT) return;
    int b = i / NT;
    int idx = (int)(g_keys[i] & 0x3FFFULL);
    g_order[i] = idx;
    g_inv[b * NT + idx] = i - b * NT;
}

// LN producing packed bf16 hi/lo pairs (128 threads, 2 cols each)
__global__ void k_ln256(const float* __restrict__ w, const float* __restrict__ bias) {
    int r = blockIdx.x, t = threadIdx.x;
    float2 v = *(const float2*)(g_q + r * DM + 2 * t);
    float mean = blockReduceSum(v.x + v.y) * (1.0f / DM);
    float x0 = v.x - mean, x1 = v.y - mean;
    float var = blockReduceSum(x0 * x0 + x1 * x1) * (1.0f / DM);
    float rs = rsqrtf(var + 1e-5f);
    float r0 = x0 * rs * w[2 * t] + bias[2 * t];
    float r1 = x1 * rs * w[2 * t + 1] + bias[2 * t + 1];
    unsigned short h0, l0, h1, l1;
    bfsplit(r0, h0, l0);
    bfsplit(r1, h1, l1);
    g_qnhi[r * (DM / 2) + t] = (unsigned)h0 | ((unsigned)h1 << 16);
    g_qnlo[r * (DM / 2) + t] = (unsigned)l0 | ((unsigned)l1 << 16);
}

// weight split + transpose: W[K][N] -> Wt hi/lo [NP][K/2] packed bf16x2
__global__ void k_splitW(const float* __restrict__ src, int K, int N, int NP) {
    int idx = blockIdx.x * blockDim.x + threadIdx.x;
    if (idx >= (K / 2) * NP) return;
    int kp = idx / NP, n = idx - kp * NP;
    float w0 = (n < N) ? src[(size_t)(2 * kp) * N + n] : 0.0f;
    float w1 = (n < N) ? src[(size_t)(2 * kp + 1) * N + n] : 0.0f;
    unsigned short h0, l0, h1, l1;
    bfsplit(w0, h0, l0);
    bfsplit(w1, h1, l1);
    g_Whi[(size_t)n * (K / 2) + kp] = (unsigned)h0 | ((unsigned)h1 << 16);
    g_Wlo[(size_t)n * (K / 2) + kp] = (unsigned)l0 | ((unsigned)l1 << 16);
}

// ---------------- bf16x3 tensor-core GEMM ----------------
// C[M,N] = A[M,K] @ B[K,N]; A packed bf16x2 hi/lo [M][K/2]; Bt packed [NP][K/2].
// Tile 128x64, k-step 32, 256 threads, 2-stage cp.async pipeline.
__device__ __forceinline__ void gemm_load_bf(
    const unsigned* __restrict__ Ahi, const unsigned* __restrict__ Alo, int K2,
    const unsigned* __restrict__ Bhi, const unsigned* __restrict__ Blo,
    int m0, int n0, int kt, unsigned* sAh, unsigned* sAl,
    unsigned* sBh, unsigned* sBl, int tid) {
    int kp0 = kt * 16;
    int r = tid >> 1, cu = (tid & 1) * 8;
    const unsigned* pah = Ahi + (size_t)(m0 + r) * K2 + kp0 + cu;
    const unsigned* pal = Alo + (size_t)(m0 + r) * K2 + kp0 + cu;
    unsigned dah = (unsigned)__cvta_generic_to_shared(sAh + r * WSTR + cu);
    unsigned dal = (unsigned)__cvta_generic_to_shared(sAl + r * WSTR + cu);
    cp16(dah, pah); cp16(dah + 16, pah + 4);
    cp16(dal, pal); cp16(dal + 16, pal + 4);
    int n = tid >> 2, cb = (tid & 3) * 4;
    cp16((unsigned)__cvta_generic_to_shared(sBh + n * WSTR + cb),
         Bhi + (size_t)(n0 + n) * K2 + kp0 + cb);
    cp16((unsigned)__cvta_generic_to_shared(sBl + n * WSTR + cb),
         Blo + (size_t)(n0 + n) * K2 + kp0 + cb);
}

__global__ __launch_bounds__(256) void k_gemm_bf(int M, int N, int K,
        const unsigned* __restrict__ Ahi, const unsigned* __restrict__ Alo,
        float* __restrict__ C, int ldc) {
    const unsigned* Bhi = g_Whi;
    const unsigned* Blo = g_Wlo;
    unsigned* sm = (unsigned*)dynsmem;
    const int ASZ = 128 * WSTR, BSZ = 64 * WSTR;
    const int STG = 2 * ASZ + 2 * BSZ;

    int m0 = blockIdx.y * 128, n0 = blockIdx.x * 64;
    int tid = threadIdx.x;
    int wid = tid >> 5, lane = tid & 31;
    int wm = (wid & 3) * 32, wn = (wid >> 2) * 32;
    int g = lane >> 2, tg = lane & 3;
    int K2 = K >> 1;
    int KT = K / 32;

    float acc[2][4][4];
    #pragma unroll
    for (int a = 0; a < 2; a++)
        #pragma unroll
        for (int b = 0; b < 4; b++)
            #pragma unroll
            for (int c = 0; c < 4; c++) acc[a][b][c] = 0.0f;

    gemm_load_bf(Ahi, Alo, K2, Bhi, Blo, m0, n0, 0,
                 sm, sm + ASZ, sm + 2 * ASZ, sm + 2 * ASZ + BSZ, tid);
    asm volatile("cp.async.commit_group;");

    for (int kt = 0; kt < KT; kt++) {
        int st = kt & 1;
        if (kt + 1 < KT) {
            int ns = st ^ 1;
            unsigned* b0 = sm + ns * STG;
            gemm_load_bf(Ahi, Alo, K2, Bhi, Blo, m0, n0, kt + 1,
                         b0, b0 + ASZ, b0 + 2 * ASZ, b0 + 2 * ASZ + BSZ, tid);
            asm volatile("cp.async.commit_group;");
            asm volatile("cp.async.wait_group 1;");
        } else {
            asm volatile("cp.async.wait_group 0;");
        }
        __syncthreads();
        unsigned* sAhi = sm + st * STG;
        unsigned* sAlo = sAhi + ASZ;
        unsigned* sBhi = sAhi + 2 * ASZ;
        unsigned* sBlo = sBhi + BSZ;
        #pragma unroll
        for (int kk2 = 0; kk2 < 16; kk2 += 8) {
            unsigned ahi[2][4], alo[2][4], bhi[4][2], blo[4][2];
            #pragma unroll
            for (int mi = 0; mi < 2; mi++) {
                int ra = (wm + mi * 16 + g) * WSTR;
                int rb = (wm + mi * 16 + g + 8) * WSTR;
                ahi[mi][0] = sAhi[ra + kk2 + tg];
                ahi[mi][1] = sAhi[rb + kk2 + tg];
                ahi[mi][2] = sAhi[ra + kk2 + 4 + tg];
                ahi[mi][3] = sAhi[rb + kk2 + 4 + tg];
                alo[mi][0] = sAlo[ra + kk2 + tg];
                alo[mi][1] = sAlo[rb + kk2 + tg];
                alo[mi][2] = sAlo[ra + kk2 + 4 + tg];
                alo[mi][3] = sAlo[rb + kk2 + 4 + tg];
            }
            #pragma unroll
            for (int nj = 0; nj < 4; nj++) {
                int rn = (wn + nj * 8 + g) * WSTR;
                bhi[nj][0] = sBhi[rn + kk2 + tg];
                bhi[nj][1] = sBhi[rn + kk2 + 4 + tg];
                blo[nj][0] = sBlo[rn + kk2 + tg];
                blo[nj][1] = sBlo[rn + kk2 + 4 + tg];
            }
            #pragma unroll
            for (int mi = 0; mi < 2; mi++)
                #pragma unroll
                for (int nj = 0; nj < 4; nj++) {
                    mma_bf16(acc[mi][nj], ahi[mi], bhi[nj][0], bhi[nj][1]);
                    mma_bf16(acc[mi][nj], ahi[mi], blo[nj][0], blo[nj][1]);
                    mma_bf16(acc[mi][nj], alo[mi], bhi[nj][0], bhi[nj][1]);
                }
        }
        __syncthreads();
    }
    #pragma unroll
    for (int mi = 0; mi < 2; mi++)
        #pragma unroll
        for (int nj = 0; nj < 4; nj++) {
            int row = m0 + wm + mi * 16 + g;
            int col = n0 + wn + nj * 8 + tg * 2;
            if (col + 1 < N) {
                *(float2*)(C + (size_t)row * ldc + col) =
                    make_float2(acc[mi][nj][0], acc[mi][nj][1]);
                *(float2*)(C + (size_t)(row + 8) * ldc + col) =
                    make_float2(acc[mi][nj][2], acc[mi][nj][3]);
            } else if (col < N) {
                C[(size_t)row * ldc + col] = acc[mi][nj][0];
                C[(size_t)(row + 8) * ldc + col] = acc[mi][nj][2];
            }
        }
}

// ---------------- conv + dt ----------------
__global__ void k_conv(const float* __restrict__ cw, const float* __restrict__ cb) {
    int r = blockIdx.x, b = blockIdx.y;
    __shared__ int tok[KER];
    if (threadIdx.x < KER) {
        int rr = r - (KER - 1) + threadIdx.x;
        tok[threadIdx.x] = (rr >= 0) ? g_order[b * NT + rr] : -1;
    }
    __syncthreads();
    for (int c = threadIdx.x; c < CD; c += blockDim.x) {
        float acc = cb[c];
        #pragma unroll
        for (int k = 0; k < KER; k++) {
            int t = tok[k];
            if (t >= 0) acc += cw[c * KER + k] * g_Z[(size_t)t * DP + DI + c];
        }
        float s = acc / (1.0f + __expf(-acc));
        g_XBC[(size_t)(b * NT + r) * CD + c] = s;
    }
}

__global__ void k_dt(const float* __restrict__ dtb, const float* __restrict__ alog) {
    int i = blockIdx.x * blockDim.x + threadIdx.x;
    if (i >= 2 * NT * NH) return;
    int b = i / (NT * NH);
    int rem = i - b * NT * NH;
    int r = rem / NH, h = rem - r * NH;
    int t = g_order[b * NT + r];
    float x = g_Z[(size_t)t * DP + DI + CD + h] + dtb[h];
    float sp = fmaxf(x, 0.0f) + log1pf(expf(-fabsf(x)));
    float A = -expf(alog[h]);
    g_dt[i] = sp;
    g_a[i] = sp * A;
}

// ---------------- chunked scan ----------------
__global__ __launch_bounds__(256) void k_scan1() {
    int c = blockIdx.x, h = blockIdx.y, b = blockIdx.z;
    __shared__ float sX[CQ * SR], sB[CQ * SR];
    __shared__ float scum[CQ], sw[CQ];
    int r0 = c * CQ, tid = threadIdx.x;
    for (int idx = tid; idx < CQ * 64; idx += 256) {
        int j = idx >> 6, p = idx & 63;
        sX[j * SR + p] = g_XBC[(size_t)(b * NT + r0 + j) * CD + h * HD + p];
        sB[j * SR + p] = g_XBC[(size_t)(b * NT + r0 + j) * CD + DI + p];
    }
    if (tid < CQ) scum[tid] = g_a[(size_t)(b * NT + r0 + tid) * NH + h];
    __syncthreads();
    if (tid == 0) {
        float s = 0.0f;
        for (int i = 0; i < CQ; i++) { s += scum[i]; scum[i] = s; }
    }
    __syncthreads();
    float slast = scum[CQ - 1];
    if (tid < CQ) {
        sw[tid] = __expf(slast - scum[tid]) * g_dt[(size_t)(b * NT + r0 + tid) * NH + h];
        g_cum[((b * NH + h) * NCH + c) * CQ + tid] = scum[tid];
    }
    if (tid == 0) g_cdec[(b * NH + h) * NCH + c] = __expf(slast);
    __syncthreads();
    int p0 = (tid & 15) * 4, s0 = (tid >> 4) * 4;
    float acc[4][4] = {};
    for (int j = 0; j < CQ; j++) {
        float4 xv = *(float4*)&sX[j * SR + p0];
        float4 bv = *(float4*)&sB[j * SR + s0];
        float w = sw[j];
        float wx[4] = {xv.x * w, xv.y * w, xv.z * w, xv.w * w};
        float bb[4] = {bv.x, bv.y, bv.z, bv.w};
        #pragma unroll
        for (int pi = 0; pi < 4; pi++)
            #pragma unroll
            for (int si = 0; si < 4; si++) acc[pi][si] += wx[pi] * bb[si];
    }
    size_t base = ((size_t)((b * NH + h) * NCH + c) * HD) * DS;
    #pragma unroll
    for (int pi = 0; pi < 4; pi++)
        *(float4*)&g_S[base + (size_t)(p0 + pi) * DS + s0] =
            make_float4(acc[pi][0], acc[pi][1], acc[pi][2], acc[pi][3]);
}

__global__ void k_scan2() {
    __shared__ float scd[NCH];
    int bh = blockIdx.x >> 4;
    int e = ((blockIdx.x & 15) << 8) + threadIdx.x;
    if (threadIdx.x < NCH) scd[threadIdx.x] = g_cdec[bh * NCH + threadIdx.x];
    __syncthreads();
    float H = 0.0f;
    for (int c = 0; c < NCH; c++) {
        size_t off = ((size_t)(bh * NCH + c)) * (HD * DS) + e;
        float s = g_S[off];
        g_Hp[off] = H;
        H = scd[c] * H + s;
    }
}

__global__ __launch_bounds__(256) void k_scan3(const float* __restrict__ Dv) {
    int c = blockIdx.x, b = blockIdx.y;
    int r0 = c * CQ, tid = threadIdx.x;
    float* sB  = dynsmem;
    float* sC  = sB  + CQ * SR;
    float* sD0 = sC  + CQ * SR;
    float* sX  = sD0 + CQ * SR;
    float* sH  = sX  + CQ * SR;
    float* sG  = sH  + CQ * SR;
    float* scum = sG + CQ * SR;
    float* sdt  = scum + CQ;
    float* seY  = sdt + CQ;

    for (int idx = tid; idx < CQ * 64; idx += 256) {
        int j = idx >> 6, s = idx & 63;
        sB[j * SR + s] = g_XBC[(size_t)(b * NT + r0 + j) * CD + DI + s];
        sC[j * SR + s] = g_XBC[(size_t)(b * NT + r0 + j) * CD + DI + DS + s];
    }
    __syncthreads();
    int i0 = (tid >> 4) * 4, j0 = (tid & 15) * 4;
    {
        float acc[4][4] = {};
        for (int sc = 0; sc < 64; sc += 4) {
            float4 Cr[4], Br[4];
            #pragma unroll
            for (int r = 0; r < 4; r++) Cr[r] = *(float4*)&sC[(i0 + r) * SR + sc];
            #pragma unroll
            for (int q = 0; q < 4; q++) Br[q] = *(float4*)&sB[(j0 + q) * SR + sc];
            #pragma unroll
            for (int r = 0; r < 4; r++) {
                float cr[4] = {Cr[r].x, Cr[r].y, Cr[r].z, Cr[r].w};
                #pragma unroll
                for (int q = 0; q < 4; q++) {
                    acc[r][q] += cr[0] * Br[q].x + cr[1] * Br[q].y +
                                 cr[2] * Br[q].z + cr[3] * Br[q].w;
                }
            }
        }
        #pragma unroll
        for (int r = 0; r < 4; r++)
            *(float4*)&sD0[(i0 + r) * SR + j0] =
                make_float4(acc[r][0], acc[r][1], acc[r][2], acc[r][3]);
    }
    __syncthreads();

    for (int h = 0; h < NH; h++) {
        for (int idx = tid; idx < CQ * 64; idx += 256) {
            int j = idx >> 6, p = idx & 63;
            sX[j * SR + p] = g_XBC[(size_t)(b * NT + r0 + j) * CD + h * HD + p];
            sH[j * SR + p] = g_Hp[((size_t)((b * NH + h) * NCH + c) * HD) * DS + idx];
        }
        if (tid < CQ) {
            float cu = g_cum[((b * NH + h) * NCH + c) * CQ + tid];
            scum[tid] = cu;
            sdt[tid] = g_dt[(size_t)(b * NT + r0 + tid) * NH + h];
            seY[tid] = __expf(cu);
        }
        __syncthreads();
        {
            #pragma unroll
            for (int r = 0; r < 4; r++) {
                float4 d = *(float4*)&sD0[(i0 + r) * SR + j0];
                float dd[4] = {d.x, d.y, d.z, d.w};
                float gv[4];
                int i = i0 + r;
                float ci = scum[i];
                #pragma unroll
                for (int q = 0; q < 4; q++) {
                    int j = j0 + q;
                    gv[q] = (j <= i) ? __expf(ci - scum[j]) * sdt[j] * dd[q] : 0.0f;
                }
                *(float4*)&sG[(i0 + r) * SR + j0] = make_float4(gv[0], gv[1], gv[2], gv[3]);
            }
        }
        __syncthreads();
        int p0 = j0;
        float acc[4][4] = {};
        for (int sc = 0; sc < 64; sc += 4) {
            float4 Cr[4], Hc[4];
            #pragma unroll
            for (int r = 0; r < 4; r++) Cr[r] = *(float4*)&sC[(i0 + r) * SR + sc];
            #pragma unroll
            for (int q = 0; q < 4; q++) Hc[q] = *(float4*)&sH[(p0 + q) * SR + sc];
            #pragma unroll
            for (int r = 0; r < 4; r++) {
                float cr[4] = {Cr[r].x, Cr[r].y, Cr[r].z, Cr[r].w};
                #pragma unroll
                for (int q = 0; q < 4; q++) {
                    acc[r][q] += cr[0] * Hc[q].x + cr[1] * Hc[q].y +
                                 cr[2] * Hc[q].z + cr[3] * Hc[q].w;
                }
            }
        }
        #pragma unroll
        for (int r = 0; r < 4; r++) {
            float e = seY[i0 + r];
            #pragma unroll
            for (int q = 0; q < 4; q++) acc[r][q] *= e;
        }
        for (int jc = 0; jc < 64; jc += 4) {
            float G4[4][4];
            #pragma unroll
            for (int r = 0; r < 4; r++) {
                float4 t = *(float4*)&sG[(i0 + r) * SR + jc];
                G4[r][0] = t.x; G4[r][1] = t.y; G4[r][2] = t.z; G4[r][3] = t.w;
            }
            #pragma unroll
            for (int q = 0; q < 4; q++) {
                float4 xv = *(float4*)&sX[(jc + q) * SR + p0];
                float xb[4] = {xv.x, xv.y, xv.z, xv.w};
                #pragma unroll
                for (int r = 0; r < 4; r++) {
                    float gq = G4[r][q];
                    #pragma unroll
                    for (int cc = 0; cc < 4; cc++) acc[r][cc] += gq * xb[cc];
                }
            }
        }
        float Dh = Dv[h];
        #pragma unroll
        for (int r = 0; r < 4; r++) {
            float4 xi = *(float4*)&sX[(i0 + r) * SR + p0];
            float4 yv = make_float4(acc[r][0] + Dh * xi.x, acc[r][1] + Dh * xi.y,
                                    acc[r][2] + Dh * xi.z, acc[r][3] + Dh * xi.w);
            *(float4*)&g_Y[(size_t)(b * NT + r0 + i0 + r) * DI + h * HD + p0] = yv;
        }
        __syncthreads();
    }
}

// ---------------- epilogue ----------------
__global__ void k_postnorm(const float* __restrict__ nw) {
    int r = blockIdx.x, b = blockIdx.y, tid = threadIdx.x;
    int t = g_order[b * NT + r];
    float v0, v1, ss;
    {
        float y0 = g_Y[(size_t)(b * NT + r) * DI + tid];
        float g0 = g_Z[(size_t)t * DP + tid];
        v0 = y0 * (g0 / (1.0f + __expf(-g0)));
        float y1 = g_Y[(size_t)(b * NT + r) * DI + tid + 256];
        float g1 = g_Z[(size_t)t * DP + tid + 256];
        v1 = y1 * (g1 / (1.0f + __expf(-g1)));
        ss = v0 * v0 + v1 * v1;
    }
    ss = blockReduceSum(ss);
    float rr = rsqrtf(ss * (1.0f / DI) + 1e-5f);
    g_Y[(size_t)(b * NT + r) * DI + tid]       = v0 * rr * nw[tid];
    g_Y[(size_t)(b * NT + r) * DI + tid + 256] = v1 * rr * nw[tid + 256];
}

// combine + bf16 split (256 threads, 2 cols each)
__global__ void k_combine() {
    int t = blockIdx.x, c = threadIdx.x;
    int r0 = g_inv[t], r1 = g_inv[NT + t];
    float2 a = *(const float2*)(g_Y + (size_t)r0 * DI + 2 * c);
    float2 bq = *(const float2*)(g_Y + (size_t)(NT + r1) * DI + 2 * c);
    float v0 = 0.5f * (a.x + bq.x);
    float v1 = 0.5f * (a.y + bq.y);
    unsigned short h0, l0, h1, l1;
    bfsplit(v0, h0, l0);
    bfsplit(v1, h1, l1);
    g_combhi[(size_t)t * (DI / 2) + c] = (unsigned)h0 | ((unsigned)h1 << 16);
    g_comblo[(size_t)t * (DI / 2) + c] = (unsigned)l0 | ((unsigned)l1 << 16);
}

__global__ void k_final(const float* __restrict__ w, const float* __restrict__ bias,
                        float* __restrict__ dout) {
    int r = blockIdx.x, c = threadIdx.x;
    float v = g_q[r * DM + c] + g_O[r * DM + c];
    float mean = blockReduceSum(v) * (1.0f / DM);
    float xc = v - mean;
    float var = blockReduceSum(xc * xc) * (1.0f / DM);
    float res = xc * rsqrtf(var + 1e-5f) * w[c] + bias[c];
    g_q[r * DM + c] = res;
    if (dout) dout[r * DM + c] = res;
}

// ---------------- launcher ----------------
extern "C" void kernel_launch(void* const* d_in, const int* in_sizes, int n_in,
                              void* d_out, int out_size) {
    (void)in_sizes; (void)n_in; (void)out_size;
    const float* query = (const float*)d_in[0];
    const float* pos   = (const float*)d_in[1];
    const float* pre_w = (const float*)d_in[2];
    const float* pre_b = (const float*)d_in[3];
    const float* fin_w = (const float*)d_in[4];
    const float* fin_b = (const float*)d_in[5];

    const int SORT_SMEM = (NT + NT / 16) * 8;
    const int GEMM_SMEM = 2 * (2 * 128 * WSTR + 2 * 64 * WSTR) * 4;
    const int SCAN3_SMEM = (6 * CQ * SR + 3 * CQ) * 4;
    cudaFuncSetAttribute(k_sort, cudaFuncAttributeMaxDynamicSharedMemorySize, SORT_SMEM);
    cudaFuncSetAttribute(k_gemm_bf, cudaFuncAttributeMaxDynamicSharedMemorySize, GEMM_SMEM);
    cudaFuncSetAttribute(k_scan3, cudaFuncAttributeMaxDynamicSharedMemorySize, SCAN3_SMEM);

    unsigned *p_qnhi, *p_qnlo, *p_combhi, *p_comblo;
    float *p_Z, *p_O;
    cudaGetSymbolAddress((void**)&p_qnhi, g_qnhi);
    cudaGetSymbolAddress((void**)&p_qnlo, g_qnlo);
    cudaGetSymbolAddress((void**)&p_combhi, g_combhi);
    cudaGetSymbolAddress((void**)&p_comblo, g_comblo);
    cudaGetSymbolAddress((void**)&p_Z, g_Z);
    cudaGetSymbolAddress((void**)&p_O, g_O);

    k_copy<<<(NT * DM + 255) / 256, 256>>>(query);
    k_minmax<<<1, 256>>>(pos);
    k_keys<<<(NT + 255) / 256, 256>>>(pos);
    k_sort<<<2, 1024, SORT_SMEM>>>();
    k_order<<<(2 * NT + 255) / 256, 256>>>();

    for (int L = 0; L < 2; L++) {
        const float* Win  = (const float*)d_in[6 + 8 * L];
        const float* cw   = (const float*)d_in[7 + 8 * L];
        const float* cb   = (const float*)d_in[8 + 8 * L];
        const float* dtb  = (const float*)d_in[9 + 8 * L];
        const float* alog = (const float*)d_in[10 + 8 * L];
        const float* Dv   = (const float*)d_in[11 + 8 * L];
        const float* nw   = (const float*)d_in[12 + 8 * L];
        const float* Wout = (const float*)d_in[13 + 8 * L];

        k_ln256<<<NT, 128>>>(pre_w, pre_b);
        k_splitW<<<((DM / 2) * NPIN + 255) / 256, 256>>>(Win, DM, DP, NPIN);
        k_gemm_bf<<<dim3(NPIN / 64, NT / 128), 256, GEMM_SMEM>>>(
            NT, DP, DM, p_qnhi, p_qnlo, p_Z, DP);
        k_conv<<<dim3(NT, 2), 256>>>(cw, cb);
        k_dt<<<(2 * NT * NH + 255) / 256, 256>>>(dtb, alog);
        k_scan1<<<dim3(NCH, NH, 2), 256>>>();
        k_scan2<<<256, 256>>>();
        k_scan3<<<dim3(NCH, 2), 256, SCAN3_SMEM>>>(Dv);
        k_postnorm<<<dim3(NT, 2), 256>>>(nw);
        k_combine<<<NT, 256>>>();
        k_splitW<<<((DI / 2) * DM + 255) / 256, 256>>>(Wout, DI, DM, DM);
        k_gemm_bf<<<dim3(DM / 64, NT / 128), 256, GEMM_SMEM>>>(
            NT, DM, DI, p_combhi, p_comblo, p_O, DM);
        k_final<<<NT, 256>>>(fin_w, fin_b, (L == 1) ? (float*)d_out : nullptr);
    }
}